// round 2
// baseline (speedup 1.0000x reference)
#include <cuda_runtime.h>
#include <math.h>

// ---------------------------------------------------------------------------
// SwinTransformerBlock3D  (B=4, D=8, H=56, W=56, C=128, WIN=(2,7,7), HEADS=4)
// No padding needed (8%2==0, 56%7==0) -> window partition + roll is a bijection
// between window rows and spatial tokens; fused into GEMM gather/scatter.
// ---------------------------------------------------------------------------

#define M_TOK 100352            // 4*8*56*56  == 1024 windows * 98 tokens
#define NWIN  1024
#define NTOK  98

// Scratch: xn | qkv | attn_out | y2 | xn2 | h1
// sizes(fl): 12845056 | 38535168 | 12845056 | 12845056 | 12845056 | 51380224
__device__ float g_buf[141295616];

// window row r -> spatial token index (roll by -SHIFT folded in).
// Forward gather (x_windows[r] = xn[token(r)]) AND inverse scatter
// (window-reverse + roll-back lands row r at the same token).
__device__ __forceinline__ int win_row_to_token(int r) {
    int win = r / 98;
    int n   = r - win * 98;
    int ww = win & 7;
    int wh = (win >> 3) & 7;
    int wd = (win >> 6) & 3;
    int b  = win >> 8;
    int id  = n / 49;
    int rem = n - id * 49;
    int ih  = rem / 7;
    int iw  = rem - ih * 7;
    int d = wd * 2 + id;
    int h = wh * 7 + ih;
    int w = ww * 7 + iw;
    int ds = d + 1;  if (ds >= 8)  ds -= 8;
    int hs = h + 3;  if (hs >= 56) hs -= 56;
    int ws = w + 3;  if (ws >= 56) ws -= 56;
    return ((b * 8 + ds) * 56 + hs) * 56 + ws;
}

// ---------------------------------------------------------------------------
// LayerNorm: warp per token (128 channels -> float4 per lane)
// ---------------------------------------------------------------------------
__global__ __launch_bounds__(256)
void ln_kernel(const float* __restrict__ x, const float* __restrict__ g,
               const float* __restrict__ beta, float* __restrict__ out) {
    int t    = blockIdx.x * 8 + (threadIdx.x >> 5);
    int lane = threadIdx.x & 31;
    size_t base = (size_t)t * 128 + lane * 4;
    float4 v = *(const float4*)(x + base);
    float s  = v.x + v.y + v.z + v.w;
    float s2 = fmaf(v.x, v.x, fmaf(v.y, v.y, fmaf(v.z, v.z, v.w * v.w)));
    #pragma unroll
    for (int o = 16; o; o >>= 1) {
        s  += __shfl_xor_sync(0xffffffffu, s,  o);
        s2 += __shfl_xor_sync(0xffffffffu, s2, o);
    }
    float mu  = s * (1.0f / 128.0f);
    float var = s2 * (1.0f / 128.0f) - mu * mu;
    float inv = rsqrtf(var + 1e-5f);
    float4 gv = *(const float4*)(g + lane * 4);
    float4 bv = *(const float4*)(beta + lane * 4);
    float4 o;
    o.x = (v.x - mu) * inv * gv.x + bv.x;
    o.y = (v.y - mu) * inv * gv.y + bv.y;
    o.z = (v.z - mu) * inv * gv.z + bv.z;
    o.w = (v.w - mu) * inv * gv.w + bv.w;
    *(float4*)(out + base) = o;
}

// ---------------------------------------------------------------------------
// fp32 GEMM: C[M,N] = epilogue(A[M,K] @ W[K,N] + bias)
// tile 128x64, BK=16, 256 threads, 8x4 microtile.
// GATHER: A rows read through win_row_to_token (LN1 out -> windowed rows)
// SCATTER: C rows (and residual rows) written through win_row_to_token
// ---------------------------------------------------------------------------
enum { EPI_BIAS = 0, EPI_GELU = 1, EPI_RES = 2 };

__device__ __forceinline__ float gelu_exact(float v) {
    return 0.5f * v * (1.0f + erff(v * 0.7071067811865476f));
}

template<int EPI, bool GATHER, bool SCATTER>
__global__ __launch_bounds__(256)
void gemm_kernel(const float* __restrict__ A, const float* __restrict__ W,
                 const float* __restrict__ bias, const float* __restrict__ res,
                 float* __restrict__ C, int M, int Nn, int K) {
    __shared__ float As[16][128];
    __shared__ float Bs[16][64];
    __shared__ int   rowmap[128];

    int tid = threadIdx.x;
    int tx  = tid & 15;
    int ty  = tid >> 4;
    int m0  = blockIdx.x * 128;
    int n0  = blockIdx.y * 64;

    if (GATHER || SCATTER) {
        if (tid < 128) rowmap[tid] = win_row_to_token(m0 + tid);
        __syncthreads();
    }

    float acc[8][4];
    #pragma unroll
    for (int i = 0; i < 8; i++)
        #pragma unroll
        for (int j = 0; j < 4; j++) acc[i][j] = 0.0f;

    for (int k0 = 0; k0 < K; k0 += 16) {
        // load A tile (128x16), 2 float4 per thread, store transposed [k][m]
        #pragma unroll
        for (int i = 0; i < 2; i++) {
            int lin = i * 256 + tid;         // float4 index 0..511
            int r   = lin >> 2;              // row 0..127
            int ks  = (lin & 3) << 2;        // 0,4,8,12
            int arow = GATHER ? rowmap[r] : (m0 + r);
            float4 a = *(const float4*)(A + (size_t)arow * K + k0 + ks);
            As[ks + 0][r] = a.x;
            As[ks + 1][r] = a.y;
            As[ks + 2][r] = a.z;
            As[ks + 3][r] = a.w;
        }
        // load B tile (16x64), 1 float4 per thread
        {
            int kk = tid >> 4;
            int ns = (tid & 15) << 2;
            *(float4*)&Bs[kk][ns] = *(const float4*)(W + (size_t)(k0 + kk) * Nn + n0 + ns);
        }
        __syncthreads();

        #pragma unroll
        for (int kk = 0; kk < 16; kk++) {
            float4 a0 = *(const float4*)&As[kk][ty * 8];
            float4 a1 = *(const float4*)&As[kk][ty * 8 + 4];
            float4 b  = *(const float4*)&Bs[kk][tx * 4];
            float av[8] = {a0.x, a0.y, a0.z, a0.w, a1.x, a1.y, a1.z, a1.w};
            float bv[4] = {b.x, b.y, b.z, b.w};
            #pragma unroll
            for (int i = 0; i < 8; i++)
                #pragma unroll
                for (int j = 0; j < 4; j++)
                    acc[i][j] = fmaf(av[i], bv[j], acc[i][j]);
        }
        __syncthreads();
    }

    float4 bv = *(const float4*)(bias + n0 + tx * 4);
    #pragma unroll
    for (int i = 0; i < 8; i++) {
        int ml   = ty * 8 + i;
        int orow = SCATTER ? rowmap[ml] : (m0 + ml);
        size_t off = (size_t)orow * Nn + n0 + tx * 4;
        float4 o;
        o.x = acc[i][0] + bv.x;
        o.y = acc[i][1] + bv.y;
        o.z = acc[i][2] + bv.z;
        o.w = acc[i][3] + bv.w;
        if (EPI == EPI_GELU) {
            o.x = gelu_exact(o.x); o.y = gelu_exact(o.y);
            o.z = gelu_exact(o.z); o.w = gelu_exact(o.w);
        }
        if (EPI == EPI_RES) {
            float4 rr = *(const float4*)(res + off);
            o.x += rr.x; o.y += rr.y; o.z += rr.z; o.w += rr.w;
        }
        *(float4*)(C + off) = o;
    }
}

// ---------------------------------------------------------------------------
// Attention: one block per (window, head). 98x98 scores + rpb bias + softmax
// + attn@v, all in shared memory. hd = 32 -> one lane per head-dim in AV.
// smem: q[98*32] | k^T[32*98] | v[98*32] | attn[98*98] = 19012 floats = 76048B
// ---------------------------------------------------------------------------
__global__ __launch_bounds__(128)
void attn_kernel(const float* __restrict__ qkv, const int* __restrict__ rel_idx,
                 const float* __restrict__ rpb, float* __restrict__ ao) {
    extern __shared__ float sm[];
    float* qs = sm;            // [98][32]
    float* kt = sm + 3136;     // [32][98]  (transposed)
    float* vs = sm + 6272;     // [98][32]
    float* at = sm + 9408;     // [98][98]

    int tid  = threadIdx.x;
    int win  = blockIdx.x >> 2;
    int head = blockIdx.x & 3;
    const float scale = 0.17677669529663687f;   // 32^-0.5

    for (int idx = tid; idx < 98 * 8; idx += 128) {
        int n  = idx >> 3;
        int d4 = (idx & 7) << 2;
        size_t base = (size_t)(win * 98 + n) * 384 + head * 32 + d4;
        float4 q = *(const float4*)(qkv + base);
        float4 k = *(const float4*)(qkv + base + 128);
        float4 v = *(const float4*)(qkv + base + 256);
        q.x *= scale; q.y *= scale; q.z *= scale; q.w *= scale;
        *(float4*)&qs[n * 32 + d4] = q;
        kt[(d4 + 0) * 98 + n] = k.x;
        kt[(d4 + 1) * 98 + n] = k.y;
        kt[(d4 + 2) * 98 + n] = k.z;
        kt[(d4 + 3) * 98 + n] = k.w;
        *(float4*)&vs[n * 32 + d4] = v;
    }
    __syncthreads();

    int warp = tid >> 5, lane = tid & 31;

    // scores + bias
    for (int n = warp; n < 98; n += 4) {
        float qr[32];
        #pragma unroll
        for (int kk = 0; kk < 32; kk++) qr[kk] = qs[n * 32 + kk];
        for (int m = lane; m < 98; m += 32) {
            float s = 0.0f;
            #pragma unroll
            for (int kk = 0; kk < 32; kk++)
                s = fmaf(qr[kk], kt[kk * 98 + m], s);
            int bi = rel_idx[n * 98 + m];
            at[n * 98 + m] = s + rpb[bi * 4 + head];
        }
    }
    __syncthreads();

    // softmax over m
    for (int n = warp; n < 98; n += 4) {
        float mx = -3.4e38f;
        for (int m = lane; m < 98; m += 32) mx = fmaxf(mx, at[n * 98 + m]);
        #pragma unroll
        for (int o = 16; o; o >>= 1) mx = fmaxf(mx, __shfl_xor_sync(0xffffffffu, mx, o));
        float sum = 0.0f;
        for (int m = lane; m < 98; m += 32) {
            float e = expf(at[n * 98 + m] - mx);
            at[n * 98 + m] = e;
            sum += e;
        }
        #pragma unroll
        for (int o = 16; o; o >>= 1) sum += __shfl_xor_sync(0xffffffffu, sum, o);
        float inv = 1.0f / sum;
        for (int m = lane; m < 98; m += 32) at[n * 98 + m] *= inv;
    }
    __syncthreads();

    // out = attn @ v   (lane = head-dim)
    for (int n = warp; n < 98; n += 4) {
        float s = 0.0f;
        #pragma unroll 7
        for (int m = 0; m < 98; m++)
            s = fmaf(at[n * 98 + m], vs[m * 32 + lane], s);
        ao[(size_t)(win * 98 + n) * 128 + head * 32 + lane] = s;
    }
}

// ---------------------------------------------------------------------------
extern "C" void kernel_launch(void* const* d_in, const int* in_sizes, int n_in,
                              void* d_out, int out_size) {
    (void)in_sizes; (void)n_in; (void)out_size;
    const float* x       = (const float*)d_in[0];
    const int*   rel_idx = (const int*)  d_in[1];
    const float* rpb     = (const float*)d_in[2];
    const float* qkv_w   = (const float*)d_in[3];
    const float* qkv_b   = (const float*)d_in[4];
    const float* proj_w  = (const float*)d_in[5];
    const float* proj_b  = (const float*)d_in[6];
    const float* ln1_g   = (const float*)d_in[7];
    const float* ln1_b   = (const float*)d_in[8];
    const float* ln2_g   = (const float*)d_in[9];
    const float* ln2_b   = (const float*)d_in[10];
    const float* mlp_w1  = (const float*)d_in[11];
    const float* mlp_b1  = (const float*)d_in[12];
    const float* mlp_w2  = (const float*)d_in[13];
    const float* mlp_b2  = (const float*)d_in[14];
    float* out = (float*)d_out;

    float* buf = nullptr;
    cudaGetSymbolAddress((void**)&buf, g_buf);
    float* xn   = buf;
    float* qkvb = buf + 12845056;
    float* ao   = buf + 51380224;
    float* y2   = buf + 64225280;
    float* xn2  = buf + 77070336;
    float* h1   = buf + 89915392;

    const int M = M_TOK;

    // 1) LN1
    ln_kernel<<<12544, 256>>>(x, ln1_g, ln1_b, xn);
    // 2) QKV GEMM (gathered rows: roll + window partition fused)
    gemm_kernel<EPI_BIAS, true, false><<<dim3(784, 6), 256>>>(
        xn, qkv_w, qkv_b, nullptr, qkvb, M, 384, 128);
    // 3) attention per (window, head)
    cudaFuncSetAttribute(attn_kernel, cudaFuncAttributeMaxDynamicSharedMemorySize, 76048);
    attn_kernel<<<4096, 128, 76048>>>(qkvb, rel_idx, rpb, ao);
    // 4) proj GEMM + residual, scattered back to spatial layout
    gemm_kernel<EPI_RES, false, true><<<dim3(784, 2), 256>>>(
        ao, proj_w, proj_b, x, y2, M, 128, 128);
    // 5) LN2
    ln_kernel<<<12544, 256>>>(y2, ln2_g, ln2_b, xn2);
    // 6) MLP1 + exact GELU
    gemm_kernel<EPI_GELU, false, false><<<dim3(784, 8), 256>>>(
        xn2, mlp_w1, mlp_b1, nullptr, h1, M, 512, 128);
    // 7) MLP2 + residual -> final output
    gemm_kernel<EPI_RES, false, false><<<dim3(784, 2), 256>>>(
        h1, mlp_w2, mlp_b2, y2, out, M, 128, 512);
}

// round 4
// speedup vs baseline: 2.3103x; 2.3103x over previous
#include <cuda_runtime.h>
#include <cuda_bf16.h>
#include <math.h>
#include <stdint.h>

// ---------------------------------------------------------------------------
// SwinTransformerBlock3D  (B=4, D=8, H=56, W=56, C=128, WIN=(2,7,7), HEADS=4)
// HMMA (mma.sync bf16) GEMMs + register-tiled fp32 attention.
// (tcgen05 is unavailable: harness PTX targets plain sm_103, which gates it.)
// ---------------------------------------------------------------------------

#define M_TOK 100352            // 4*8*56*56 == 1024 windows * 98 tokens

__device__ __nv_bfloat16 g_xn [(size_t)M_TOK*128];   // LN1 out, window order
__device__ __nv_bfloat16 g_qkv[(size_t)M_TOK*384];   // qkv, window order
__device__ __nv_bfloat16 g_ao [(size_t)M_TOK*128];   // attn out, window order
__device__ float         g_y2 [(size_t)M_TOK*128];   // x + proj (spatial)
__device__ __nv_bfloat16 g_xn2[(size_t)M_TOK*128];   // LN2 out (spatial)
__device__ __nv_bfloat16 g_h1 [(size_t)M_TOK*512];   // gelu(mlp1)
__device__ __nv_bfloat16 g_wt [196608];              // bf16 weights [K][N]
__device__ float         g_btab[4*98*98];            // rpb[rel_idx] per head

// window row r -> spatial token (roll -SHIFT folded in); also its own inverse
// for the scatter (window-reverse + roll-back).
__device__ __forceinline__ int win_row_to_token(int r) {
    int win = r / 98;
    int n   = r - win * 98;
    int ww = win & 7;
    int wh = (win >> 3) & 7;
    int wd = (win >> 6) & 3;
    int b  = win >> 8;
    int id  = n / 49;
    int rem = n - id * 49;
    int ih  = rem / 7;
    int iw  = rem - ih * 7;
    int d = wd * 2 + id;
    int h = wh * 7 + ih;
    int w = ww * 7 + iw;
    int ds = d + 1;  if (ds >= 8)  ds -= 8;
    int hs = h + 3;  if (hs >= 56) hs -= 56;
    int ws = w + 3;  if (ws >= 56) ws -= 56;
    return ((b * 8 + ds) * 56 + hs) * 56 + ws;
}

// ---------------------------------------------------------------------------
// helpers
// ---------------------------------------------------------------------------
__device__ __forceinline__ uint32_t cvta_smem(const void* p) {
    uint32_t a;
    asm("{ .reg .u64 t; cvta.to.shared.u64 t, %1; cvt.u32.u64 %0, t; }"
        : "=r"(a) : "l"(p));
    return a;
}
__device__ __forceinline__ uint32_t packbf(float a, float b) {
    __nv_bfloat162 t = __floats2bfloat162_rn(a, b);
    return *reinterpret_cast<uint32_t*>(&t);
}
__device__ __forceinline__ float4 ld_bf16x4(const __nv_bfloat16* p) {
    uint2 u = *(const uint2*)p;
    __nv_bfloat162 a = *reinterpret_cast<__nv_bfloat162*>(&u.x);
    __nv_bfloat162 b = *reinterpret_cast<__nv_bfloat162*>(&u.y);
    float2 fa = __bfloat1622float2(a);
    float2 fb = __bfloat1622float2(b);
    return make_float4(fa.x, fa.y, fb.x, fb.y);
}
__device__ __forceinline__ void ldmx4(uint32_t* r, uint32_t addr) {
    asm volatile("ldmatrix.sync.aligned.m8n8.x4.shared.b16 {%0,%1,%2,%3}, [%4];"
        : "=r"(r[0]), "=r"(r[1]), "=r"(r[2]), "=r"(r[3]) : "r"(addr));
}
__device__ __forceinline__ void ldmx4t(uint32_t* r, uint32_t addr) {
    asm volatile("ldmatrix.sync.aligned.m8n8.x4.trans.shared.b16 {%0,%1,%2,%3}, [%4];"
        : "=r"(r[0]), "=r"(r[1]), "=r"(r[2]), "=r"(r[3]) : "r"(addr));
}
__device__ __forceinline__ void mma16816(float* d, const uint32_t* a, const uint32_t* b) {
    asm volatile("mma.sync.aligned.m16n8k16.row.col.f32.bf16.bf16.f32 "
        "{%0,%1,%2,%3}, {%4,%5,%6,%7}, {%8,%9}, {%0,%1,%2,%3};"
        : "+f"(d[0]), "+f"(d[1]), "+f"(d[2]), "+f"(d[3])
        : "r"(a[0]), "r"(a[1]), "r"(a[2]), "r"(a[3]), "r"(b[0]), "r"(b[1]));
}
__device__ __forceinline__ float gelu_exact(float v) {
    return 0.5f * v * (1.0f + erff(v * 0.7071067811865476f));
}

// ---------------------------------------------------------------------------
// Prep kernels
// ---------------------------------------------------------------------------
__global__ void convert_w(const float* __restrict__ w, __nv_bfloat16* __restrict__ wt,
                          int total) {
    int idx = blockIdx.x * 256 + threadIdx.x;
    if (idx < total) wt[idx] = __float2bfloat16(w[idx]);
}

__global__ void build_bias(const int* __restrict__ rel_idx, const float* __restrict__ rpb,
                           float* __restrict__ btab) {
    int i = blockIdx.x * 256 + threadIdx.x;
    if (i >= 4 * 98 * 98) return;
    int h = i / 9604, nm = i - h * 9604;
    btab[i] = rpb[rel_idx[nm] * 4 + h];
}

// ---------------------------------------------------------------------------
// LayerNorm -> bf16 (optionally gathered into window order)
// ---------------------------------------------------------------------------
template<bool GATHER>
__global__ __launch_bounds__(256)
void ln_bf16(const float* __restrict__ x, const float* __restrict__ g,
             const float* __restrict__ beta, __nv_bfloat16* __restrict__ out) {
    int r    = blockIdx.x * 8 + (threadIdx.x >> 5);
    int lane = threadIdx.x & 31;
    int src  = GATHER ? win_row_to_token(r) : r;
    float4 v = *(const float4*)(x + (size_t)src * 128 + lane * 4);
    float s  = v.x + v.y + v.z + v.w;
    float s2 = fmaf(v.x, v.x, fmaf(v.y, v.y, fmaf(v.z, v.z, v.w * v.w)));
    #pragma unroll
    for (int o = 16; o; o >>= 1) {
        s  += __shfl_xor_sync(0xffffffffu, s,  o);
        s2 += __shfl_xor_sync(0xffffffffu, s2, o);
    }
    float mu  = s * (1.0f / 128.0f);
    float var = s2 * (1.0f / 128.0f) - mu * mu;
    float inv = rsqrtf(var + 1e-5f);
    float4 gv = *(const float4*)(g + lane * 4);
    float4 bv = *(const float4*)(beta + lane * 4);
    uint2 u;
    u.x = packbf((v.x - mu) * inv * gv.x + bv.x, (v.y - mu) * inv * gv.y + bv.y);
    u.y = packbf((v.z - mu) * inv * gv.z + bv.z, (v.w - mu) * inv * gv.w + bv.w);
    *(uint2*)(out + (size_t)r * 128 + lane * 4) = u;
}

// ---------------------------------------------------------------------------
// HMMA bf16 GEMM: C[M,N] = epi(A[M,K] @ W[K,N] + bias)
// CTA 128x128, 256 threads (8 warps, warp tile 32x64), K-chunk 32.
// A row-major bf16, W row-major bf16 (ldmatrix.trans for B operand).
// ---------------------------------------------------------------------------
enum { EPI_BIAS = 0, EPI_GELU = 1, EPI_RES = 2 };

template<int EPI, bool SCATTER, bool OUTBF16>
__global__ __launch_bounds__(256)
void gemm_hmma(const __nv_bfloat16* __restrict__ A, const __nv_bfloat16* __restrict__ W,
               const float* __restrict__ bias, const float* __restrict__ res,
               void* __restrict__ Cout, int Nn, int K) {
    __shared__ __nv_bfloat16 As[128][40];    // 32 + 8 pad
    __shared__ __nv_bfloat16 Bs[32][136];    // 128 + 8 pad
    __shared__ int   rowmap[128];
    __shared__ float sbias[128];

    int tid = threadIdx.x, lane = tid & 31, wid = tid >> 5;
    int wm = wid & 3, wn = wid >> 2;         // warp tile: rows wm*32, cols wn*64
    int m0 = blockIdx.x * 128, n0 = blockIdx.y * 128;

    if (tid < 128) {
        sbias[tid] = bias[n0 + tid];
        if (SCATTER) rowmap[tid] = win_row_to_token(m0 + tid);
    }

    float acc[2][8][4];
    #pragma unroll
    for (int mi = 0; mi < 2; mi++)
        #pragma unroll
        for (int ni = 0; ni < 8; ni++)
            #pragma unroll
            for (int j = 0; j < 4; j++) acc[mi][ni][j] = 0.0f;

    // per-thread ldmatrix base addresses
    uint32_t aAddr = cvta_smem(&As[wm * 32 + (lane & 15)][(lane >> 4) * 8]);
    uint32_t bAddr = cvta_smem(&Bs[(lane & 15)][wn * 64 + (lane >> 4) * 8]);

    for (int kc = 0; kc < K; kc += 32) {
        // A tile 128x32: 2 x uint4 per thread
        #pragma unroll
        for (int i = 0; i < 2; i++) {
            int idx = i * 256 + tid;
            int row = idx >> 2, seg = idx & 3;
            *(uint4*)&As[row][seg * 8] =
                *(const uint4*)(A + (size_t)(m0 + row) * K + kc + seg * 8);
        }
        // B tile 32x128: 2 x uint4 per thread
        #pragma unroll
        for (int i = 0; i < 2; i++) {
            int idx = i * 256 + tid;
            int row = idx >> 4, seg = idx & 15;
            *(uint4*)&Bs[row][seg * 8] =
                *(const uint4*)(W + (size_t)(kc + row) * Nn + n0 + seg * 8);
        }
        __syncthreads();

        #pragma unroll
        for (int ks = 0; ks < 32; ks += 16) {
            uint32_t aF[2][4];
            #pragma unroll
            for (int mi = 0; mi < 2; mi++)
                ldmx4(aF[mi], aAddr + (mi * 16) * 80u + ks * 2u);
            uint32_t bF[8][2];
            #pragma unroll
            for (int np = 0; np < 4; np++) {
                uint32_t r[4];
                ldmx4t(r, bAddr + ks * 272u + np * 32u);
                bF[2 * np    ][0] = r[0]; bF[2 * np    ][1] = r[1];
                bF[2 * np + 1][0] = r[2]; bF[2 * np + 1][1] = r[3];
            }
            #pragma unroll
            for (int mi = 0; mi < 2; mi++)
                #pragma unroll
                for (int ni = 0; ni < 8; ni++)
                    mma16816(acc[mi][ni], aF[mi], bF[ni]);
        }
        __syncthreads();
    }

    // epilogue straight from fragments
    int g  = lane >> 2, t4 = lane & 3;
    #pragma unroll
    for (int mi = 0; mi < 2; mi++) {
        int rl = wm * 32 + mi * 16 + g;
        int r0 = SCATTER ? rowmap[rl]     : (m0 + rl);
        int r1 = SCATTER ? rowmap[rl + 8] : (m0 + rl + 8);
        #pragma unroll
        for (int ni = 0; ni < 8; ni++) {
            int cl = wn * 64 + ni * 8 + t4 * 2;
            float b0 = sbias[cl], b1 = sbias[cl + 1];
            float v00 = acc[mi][ni][0] + b0, v01 = acc[mi][ni][1] + b1;
            float v10 = acc[mi][ni][2] + b0, v11 = acc[mi][ni][3] + b1;
            if (EPI == EPI_GELU) {
                v00 = gelu_exact(v00); v01 = gelu_exact(v01);
                v10 = gelu_exact(v10); v11 = gelu_exact(v11);
            }
            size_t o0 = (size_t)r0 * Nn + n0 + cl;
            size_t o1 = (size_t)r1 * Nn + n0 + cl;
            if (EPI == EPI_RES) {
                float2 q0 = *(const float2*)(res + o0);
                float2 q1 = *(const float2*)(res + o1);
                v00 += q0.x; v01 += q0.y; v10 += q1.x; v11 += q1.y;
            }
            if (OUTBF16) {
                *(uint32_t*)((__nv_bfloat16*)Cout + o0) = packbf(v00, v01);
                *(uint32_t*)((__nv_bfloat16*)Cout + o1) = packbf(v10, v11);
            } else {
                *(float2*)((float*)Cout + o0) = make_float2(v00, v01);
                *(float2*)((float*)Cout + o1) = make_float2(v10, v11);
            }
        }
    }
}

// ---------------------------------------------------------------------------
// Attention: one block per (window, head), 128 threads.
// smem floats: qs[98][32] | kt[32][128] | vs[100][32] | at[98][104] | sinv[98]
// ---------------------------------------------------------------------------
#define AQS 0
#define AKT 3136
#define AVS 7232
#define AAT 10432
#define ASI 20624
#define ASMEM ((20624 + 98) * 4 + 56)   // 82944

__global__ __launch_bounds__(128)
void attn_kernel(const __nv_bfloat16* __restrict__ qkv, const float* __restrict__ btab,
                 __nv_bfloat16* __restrict__ ao) {
    extern __shared__ float smf[];
    float* qs = smf + AQS;
    float* kt = smf + AKT;
    float* vs = smf + AVS;
    float* at = smf + AAT;
    float* si = smf + ASI;

    int tid = threadIdx.x, warp = tid >> 5, lane = tid & 31;
    int win = blockIdx.x >> 2, head = blockIdx.x & 3;
    const float scale = 0.17677669529663687f;
    const float* bt = btab + head * 9604;

    // load q,k,v
    for (int idx = tid; idx < 98 * 8; idx += 128) {
        int n = idx >> 3, d4 = (idx & 7) << 2;
        const __nv_bfloat16* base = qkv + (size_t)(win * 98 + n) * 384 + head * 32 + d4;
        float4 q = ld_bf16x4(base);
        float4 k = ld_bf16x4(base + 128);
        float4 v = ld_bf16x4(base + 256);
        q.x *= scale; q.y *= scale; q.z *= scale; q.w *= scale;
        *(float4*)&qs[n * 32 + d4] = q;
        kt[(d4 + 0) * 128 + n] = k.x;
        kt[(d4 + 1) * 128 + n] = k.y;
        kt[(d4 + 2) * 128 + n] = k.z;
        kt[(d4 + 3) * 128 + n] = k.w;
        *(float4*)&vs[n * 32 + d4] = v;
    }
    for (int idx = tid; idx < 32 * 30; idx += 128) {       // zero kt cols 98..127
        int kk = idx / 30, m = 98 + idx - (idx / 30) * 30;
        kt[kk * 128 + m] = 0.0f;
    }
    if (tid < 64) vs[3136 + tid] = 0.0f;                   // zero vs rows 98,99
    __syncthreads();

    // scores: warp tiles of 8 n-rows x 32 m (lane = m)
    for (int t = warp; t < 13; t += 4) {
        int n0 = t * 8;
        for (int mc = 0; mc < 4; mc++) {
            int m = mc * 32 + lane;
            float acc[8] = {0,0,0,0,0,0,0,0};
            #pragma unroll
            for (int kg = 0; kg < 8; kg++) {
                float k0 = kt[(kg * 4 + 0) * 128 + m];
                float k1 = kt[(kg * 4 + 1) * 128 + m];
                float k2 = kt[(kg * 4 + 2) * 128 + m];
                float k3 = kt[(kg * 4 + 3) * 128 + m];
                #pragma unroll
                for (int i = 0; i < 8; i++) {
                    float4 qf = *(const float4*)&qs[(n0 + i) * 32 + kg * 4];
                    acc[i] = fmaf(qf.x, k0, fmaf(qf.y, k1, fmaf(qf.z, k2, fmaf(qf.w, k3, acc[i]))));
                }
            }
            if (m < 104) {
                #pragma unroll
                for (int i = 0; i < 8; i++) {
                    int n = n0 + i;
                    if (n >= 98) break;
                    float val = 0.0f;
                    if (m < 98) val = acc[i] + bt[n * 98 + m];
                    at[n * 104 + m] = val;
                }
            }
        }
    }
    __syncthreads();

    // softmax (no max subtraction: |score| << 10), inv folded into AV
    for (int n = warp; n < 98; n += 4) {
        float s = 0.0f;
        #pragma unroll
        for (int mc = 0; mc < 4; mc++) {
            int m = mc * 32 + lane;
            if (m < 98) {
                float e = __expf(at[n * 104 + m]);
                at[n * 104 + m] = e;
                s += e;
            }
        }
        #pragma unroll
        for (int o = 16; o; o >>= 1) s += __shfl_xor_sync(0xffffffffu, s, o);
        if (lane == 0) si[n] = 1.0f / s;
    }
    __syncthreads();

    // AV: m-outer, at float4 broadcasts, lane = head-dim
    float acc[25];
    #pragma unroll
    for (int i = 0; i < 25; i++) acc[i] = 0.0f;
    for (int m4 = 0; m4 < 25; m4++) {
        float v0 = vs[(4 * m4 + 0) * 32 + lane];
        float v1 = vs[(4 * m4 + 1) * 32 + lane];
        float v2 = vs[(4 * m4 + 2) * 32 + lane];
        float v3 = vs[(4 * m4 + 3) * 32 + lane];
        #pragma unroll
        for (int i = 0; i < 25; i++) {
            int n = warp + 4 * i;
            if (n < 98) {
                float4 a4 = *(const float4*)&at[n * 104 + 4 * m4];
                acc[i] = fmaf(a4.x, v0, fmaf(a4.y, v1, fmaf(a4.z, v2, fmaf(a4.w, v3, acc[i]))));
            }
        }
    }
    #pragma unroll
    for (int i = 0; i < 25; i++) {
        int n = warp + 4 * i;
        if (n < 98)
            ao[(size_t)(win * 98 + n) * 128 + head * 32 + lane] =
                __float2bfloat16(acc[i] * si[n]);
    }
}

// ---------------------------------------------------------------------------
extern "C" void kernel_launch(void* const* d_in, const int* in_sizes, int n_in,
                              void* d_out, int out_size) {
    (void)in_sizes; (void)n_in; (void)out_size;
    const float* x       = (const float*)d_in[0];
    const int*   rel_idx = (const int*)  d_in[1];
    const float* rpb     = (const float*)d_in[2];
    const float* qkv_w   = (const float*)d_in[3];
    const float* qkv_b   = (const float*)d_in[4];
    const float* proj_w  = (const float*)d_in[5];
    const float* proj_b  = (const float*)d_in[6];
    const float* ln1_g   = (const float*)d_in[7];
    const float* ln1_b   = (const float*)d_in[8];
    const float* ln2_g   = (const float*)d_in[9];
    const float* ln2_b   = (const float*)d_in[10];
    const float* mlp_w1  = (const float*)d_in[11];
    const float* mlp_b1  = (const float*)d_in[12];
    const float* mlp_w2  = (const float*)d_in[13];
    const float* mlp_b2  = (const float*)d_in[14];
    float* out = (float*)d_out;

    __nv_bfloat16 *xn, *qkvb, *ao, *xn2, *h1, *wt;
    float *y2, *btab;
    cudaGetSymbolAddress((void**)&xn,   g_xn);
    cudaGetSymbolAddress((void**)&qkvb, g_qkv);
    cudaGetSymbolAddress((void**)&ao,   g_ao);
    cudaGetSymbolAddress((void**)&y2,   g_y2);
    cudaGetSymbolAddress((void**)&xn2,  g_xn2);
    cudaGetSymbolAddress((void**)&h1,   g_h1);
    cudaGetSymbolAddress((void**)&wt,   g_wt);
    cudaGetSymbolAddress((void**)&btab, g_btab);
    __nv_bfloat16* wt_qkv = wt;             // [128][384]
    __nv_bfloat16* wt_prj = wt + 49152;     // [128][128]
    __nv_bfloat16* wt_m1  = wt + 65536;     // [128][512]
    __nv_bfloat16* wt_m2  = wt + 131072;    // [512][128]

    cudaFuncSetAttribute(attn_kernel, cudaFuncAttributeMaxDynamicSharedMemorySize, ASMEM);

    // weight bf16 casts + bias table
    convert_w<<<(128*384 + 255) / 256, 256>>>(qkv_w,  wt_qkv, 128*384);
    convert_w<<<(128*128 + 255) / 256, 256>>>(proj_w, wt_prj, 128*128);
    convert_w<<<(128*512 + 255) / 256, 256>>>(mlp_w1, wt_m1,  128*512);
    convert_w<<<(512*128 + 255) / 256, 256>>>(mlp_w2, wt_m2,  512*128);
    build_bias<<<(4*9604 + 255) / 256, 256>>>(rel_idx, rpb, btab);

    // 1) LN1 (gathered into window order, bf16)
    ln_bf16<true><<<12544, 256>>>(x, ln1_g, ln1_b, xn);
    // 2) QKV GEMM (bf16 out)
    gemm_hmma<EPI_BIAS, false, true><<<dim3(784, 3), 256>>>(
        xn, wt_qkv, qkv_b, nullptr, qkvb, 384, 128);
    // 3) attention
    attn_kernel<<<4096, 128, ASMEM>>>(qkvb, btab, ao);
    // 4) proj GEMM + residual, scattered to spatial
    gemm_hmma<EPI_RES, true, false><<<dim3(784, 1), 256>>>(
        ao, wt_prj, proj_b, x, y2, 128, 128);
    // 5) LN2
    ln_bf16<false><<<12544, 256>>>(y2, ln2_g, ln2_b, xn2);
    // 6) MLP1 + GELU (bf16 out)
    gemm_hmma<EPI_GELU, false, true><<<dim3(784, 4), 256>>>(
        xn2, wt_m1, mlp_b1, nullptr, h1, 512, 128);
    // 7) MLP2 + residual -> output
    gemm_hmma<EPI_RES, false, false><<<dim3(784, 1), 256>>>(
        h1, wt_m2, mlp_b2, y2, out, 128, 512);
}

// round 5
// speedup vs baseline: 4.6707x; 2.0217x over previous
#include <cuda_runtime.h>
#include <cuda_bf16.h>
#include <math.h>
#include <stdint.h>

// ---------------------------------------------------------------------------
// SwinTransformerBlock3D  (B=4, D=8, H=56, W=56, C=128, WIN=(2,7,7), HEADS=4)
// HMMA bf16 GEMMs (cp.async double-buffered) + HMMA register-resident attention.
// ---------------------------------------------------------------------------

#define M_TOK 100352            // 4*8*56*56 == 1024 windows * 98 tokens

__device__ __nv_bfloat16 g_xn [(size_t)M_TOK*128];   // LN1 out, window order
__device__ __nv_bfloat16 g_qkv[(size_t)M_TOK*384];   // qkv, window order
__device__ __nv_bfloat16 g_ao [(size_t)M_TOK*128];   // attn out, window order
__device__ float         g_y2 [(size_t)M_TOK*128];   // x + proj (spatial)
__device__ __nv_bfloat16 g_xn2[(size_t)M_TOK*128];   // LN2 out (spatial)
__device__ __nv_bfloat16 g_h1 [(size_t)M_TOK*512];   // gelu(mlp1)
__device__ __nv_bfloat16 g_wt [196608];              // bf16 weights [K][N]
__device__ float         g_btab[4*98*112];           // log2e * rpb[rel_idx], padded

// window row r -> spatial token (roll -SHIFT folded in); self-inverse mapping.
__device__ __forceinline__ int win_row_to_token(int r) {
    int win = r / 98;
    int n   = r - win * 98;
    int ww = win & 7;
    int wh = (win >> 3) & 7;
    int wd = (win >> 6) & 3;
    int b  = win >> 8;
    int id  = n / 49;
    int rem = n - id * 49;
    int ih  = rem / 7;
    int iw  = rem - ih * 7;
    int d = wd * 2 + id;
    int h = wh * 7 + ih;
    int w = ww * 7 + iw;
    int ds = d + 1;  if (ds >= 8)  ds -= 8;
    int hs = h + 3;  if (hs >= 56) hs -= 56;
    int ws = w + 3;  if (ws >= 56) ws -= 56;
    return ((b * 8 + ds) * 56 + hs) * 56 + ws;
}

// ---------------------------------------------------------------------------
// helpers
// ---------------------------------------------------------------------------
__device__ __forceinline__ uint32_t cvta_smem(const void* p) {
    uint32_t a;
    asm("{ .reg .u64 t; cvta.to.shared.u64 t, %1; cvt.u32.u64 %0, t; }"
        : "=r"(a) : "l"(p));
    return a;
}
__device__ __forceinline__ uint32_t packbf(float a, float b) {
    __nv_bfloat162 t = __floats2bfloat162_rn(a, b);
    return *reinterpret_cast<uint32_t*>(&t);
}
__device__ __forceinline__ void ldmx4(uint32_t* r, uint32_t addr) {
    asm volatile("ldmatrix.sync.aligned.m8n8.x4.shared.b16 {%0,%1,%2,%3}, [%4];"
        : "=r"(r[0]), "=r"(r[1]), "=r"(r[2]), "=r"(r[3]) : "r"(addr));
}
__device__ __forceinline__ void ldmx4t(uint32_t* r, uint32_t addr) {
    asm volatile("ldmatrix.sync.aligned.m8n8.x4.trans.shared.b16 {%0,%1,%2,%3}, [%4];"
        : "=r"(r[0]), "=r"(r[1]), "=r"(r[2]), "=r"(r[3]) : "r"(addr));
}
__device__ __forceinline__ void mma16816(float* d, const uint32_t* a, const uint32_t* b) {
    asm volatile("mma.sync.aligned.m16n8k16.row.col.f32.bf16.bf16.f32 "
        "{%0,%1,%2,%3}, {%4,%5,%6,%7}, {%8,%9}, {%0,%1,%2,%3};"
        : "+f"(d[0]), "+f"(d[1]), "+f"(d[2]), "+f"(d[3])
        : "r"(a[0]), "r"(a[1]), "r"(a[2]), "r"(a[3]), "r"(b[0]), "r"(b[1]));
}
__device__ __forceinline__ void mma16816b(float* d, const uint32_t* a,
                                          uint32_t b0, uint32_t b1) {
    asm volatile("mma.sync.aligned.m16n8k16.row.col.f32.bf16.bf16.f32 "
        "{%0,%1,%2,%3}, {%4,%5,%6,%7}, {%8,%9}, {%0,%1,%2,%3};"
        : "+f"(d[0]), "+f"(d[1]), "+f"(d[2]), "+f"(d[3])
        : "r"(a[0]), "r"(a[1]), "r"(a[2]), "r"(a[3]), "r"(b0), "r"(b1));
}
__device__ __forceinline__ void cp16(const void* smem_dst, const void* gsrc) {
    uint32_t d = cvta_smem(smem_dst);
    asm volatile("cp.async.cg.shared.global [%0], [%1], 16;" :: "r"(d), "l"(gsrc));
}
#define CP_COMMIT()  asm volatile("cp.async.commit_group;" ::: "memory")
#define CP_WAIT1()   asm volatile("cp.async.wait_group 1;" ::: "memory")
__device__ __forceinline__ float gelu_exact(float v) {
    return 0.5f * v * (1.0f + erff(v * 0.7071067811865476f));
}

// ---------------------------------------------------------------------------
// Prep kernels
// ---------------------------------------------------------------------------
__global__ void convert_w(const float* __restrict__ w, __nv_bfloat16* __restrict__ wt,
                          int total) {
    int idx = blockIdx.x * 256 + threadIdx.x;
    if (idx < total) wt[idx] = __float2bfloat16(w[idx]);
}

__global__ void build_bias(const int* __restrict__ rel_idx, const float* __restrict__ rpb,
                           float* __restrict__ btab) {
    int i = blockIdx.x * 256 + threadIdx.x;
    if (i >= 4 * 98 * 112) return;
    int h = i / 10976, rem = i - h * 10976;
    int row = rem / 112, col = rem - row * 112;
    float v = 0.0f;
    if (col < 98) v = rpb[rel_idx[row * 98 + col] * 4 + h] * 1.4426950408889634f;
    btab[i] = v;
}

// ---------------------------------------------------------------------------
// LayerNorm -> bf16 (optionally gathered into window order)
// ---------------------------------------------------------------------------
template<bool GATHER>
__global__ __launch_bounds__(256)
void ln_bf16(const float* __restrict__ x, const float* __restrict__ g,
             const float* __restrict__ beta, __nv_bfloat16* __restrict__ out) {
    int r    = blockIdx.x * 8 + (threadIdx.x >> 5);
    int lane = threadIdx.x & 31;
    int src  = GATHER ? win_row_to_token(r) : r;
    float4 v = *(const float4*)(x + (size_t)src * 128 + lane * 4);
    float s  = v.x + v.y + v.z + v.w;
    float s2 = fmaf(v.x, v.x, fmaf(v.y, v.y, fmaf(v.z, v.z, v.w * v.w)));
    #pragma unroll
    for (int o = 16; o; o >>= 1) {
        s  += __shfl_xor_sync(0xffffffffu, s,  o);
        s2 += __shfl_xor_sync(0xffffffffu, s2, o);
    }
    float mu  = s * (1.0f / 128.0f);
    float var = s2 * (1.0f / 128.0f) - mu * mu;
    float inv = rsqrtf(var + 1e-5f);
    float4 gv = *(const float4*)(g + lane * 4);
    float4 bv = *(const float4*)(beta + lane * 4);
    uint2 u;
    u.x = packbf((v.x - mu) * inv * gv.x + bv.x, (v.y - mu) * inv * gv.y + bv.y);
    u.y = packbf((v.z - mu) * inv * gv.z + bv.z, (v.w - mu) * inv * gv.w + bv.w);
    *(uint2*)(out + (size_t)r * 128 + lane * 4) = u;
}

// ---------------------------------------------------------------------------
// HMMA bf16 GEMM: C[M,N] = epi(A[M,K] @ W[K,N] + bias)
// CTA 128x128, 256 threads (8 warps, warp tile 32x64), K-chunk 32,
// cp.async 2-stage double buffering.
// ---------------------------------------------------------------------------
enum { EPI_BIAS = 0, EPI_GELU = 1, EPI_RES = 2 };

template<int EPI, bool SCATTER, bool OUTBF16>
__global__ __launch_bounds__(256)
void gemm_hmma(const __nv_bfloat16* __restrict__ A, const __nv_bfloat16* __restrict__ W,
               const float* __restrict__ bias, const float* __restrict__ res,
               void* __restrict__ Cout, int Nn, int K) {
    __shared__ __nv_bfloat16 As[2][128][40];   // 32 + 8 pad
    __shared__ __nv_bfloat16 Bs[2][32][136];   // 128 + 8 pad
    __shared__ int   rowmap[128];
    __shared__ float sbias[128];

    int tid = threadIdx.x, lane = tid & 31, wid = tid >> 5;
    int wm = wid & 3, wn = wid >> 2;
    int m0 = blockIdx.x * 128, n0 = blockIdx.y * 128;

    if (tid < 128) {
        sbias[tid] = bias[n0 + tid];
        if (SCATTER) rowmap[tid] = win_row_to_token(m0 + tid);
    }

    int arow = tid >> 2, aseg = tid & 3;      // A: 2 iters cover 128 rows
    int brow = tid >> 4, bseg = tid & 15;     // B: 2 iters cover 32 rows

    float acc[2][8][4];
    #pragma unroll
    for (int mi = 0; mi < 2; mi++)
        #pragma unroll
        for (int ni = 0; ni < 8; ni++)
            #pragma unroll
            for (int j = 0; j < 4; j++) acc[mi][ni][j] = 0.0f;

    uint32_t aAddr = cvta_smem(&As[0][wm * 32 + (lane & 15)][(lane >> 4) * 8]);
    uint32_t bAddr = cvta_smem(&Bs[0][(lane & 15)][wn * 64 + (lane >> 4) * 8]);

    // prologue: stage 0
    #pragma unroll
    for (int i = 0; i < 2; i++)
        cp16(&As[0][arow + i * 64][aseg * 8], A + (size_t)(m0 + arow + i * 64) * K + aseg * 8);
    #pragma unroll
    for (int i = 0; i < 2; i++)
        cp16(&Bs[0][brow + i * 16][bseg * 8], W + (size_t)(brow + i * 16) * Nn + n0 + bseg * 8);
    CP_COMMIT();

    int nk = K >> 5;
    for (int c = 0; c < nk; c++) {
        if (c + 1 < nk) {
            int kc = (c + 1) << 5, s = (c + 1) & 1;
            #pragma unroll
            for (int i = 0; i < 2; i++)
                cp16(&As[s][arow + i * 64][aseg * 8],
                     A + (size_t)(m0 + arow + i * 64) * K + kc + aseg * 8);
            #pragma unroll
            for (int i = 0; i < 2; i++)
                cp16(&Bs[s][brow + i * 16][bseg * 8],
                     W + (size_t)(kc + brow + i * 16) * Nn + n0 + bseg * 8);
        }
        CP_COMMIT();
        CP_WAIT1();
        __syncthreads();

        uint32_t aOff = aAddr + (c & 1) * 10240u;
        uint32_t bOff = bAddr + (c & 1) * 8704u;
        #pragma unroll
        for (int ks = 0; ks < 32; ks += 16) {
            uint32_t aF[2][4];
            #pragma unroll
            for (int mi = 0; mi < 2; mi++)
                ldmx4(aF[mi], aOff + (mi * 16) * 80u + ks * 2u);
            uint32_t bF[8][2];
            #pragma unroll
            for (int np = 0; np < 4; np++) {
                uint32_t r[4];
                ldmx4t(r, bOff + ks * 272u + np * 32u);
                bF[2 * np    ][0] = r[0]; bF[2 * np    ][1] = r[1];
                bF[2 * np + 1][0] = r[2]; bF[2 * np + 1][1] = r[3];
            }
            #pragma unroll
            for (int mi = 0; mi < 2; mi++)
                #pragma unroll
                for (int ni = 0; ni < 8; ni++)
                    mma16816(acc[mi][ni], aF[mi], bF[ni]);
        }
        __syncthreads();
    }

    // epilogue straight from fragments
    int g  = lane >> 2, t4 = lane & 3;
    #pragma unroll
    for (int mi = 0; mi < 2; mi++) {
        int rl = wm * 32 + mi * 16 + g;
        int r0 = SCATTER ? rowmap[rl]     : (m0 + rl);
        int r1 = SCATTER ? rowmap[rl + 8] : (m0 + rl + 8);
        #pragma unroll
        for (int ni = 0; ni < 8; ni++) {
            int cl = wn * 64 + ni * 8 + t4 * 2;
            float b0 = sbias[cl], b1 = sbias[cl + 1];
            float v00 = acc[mi][ni][0] + b0, v01 = acc[mi][ni][1] + b1;
            float v10 = acc[mi][ni][2] + b0, v11 = acc[mi][ni][3] + b1;
            if (EPI == EPI_GELU) {
                v00 = gelu_exact(v00); v01 = gelu_exact(v01);
                v10 = gelu_exact(v10); v11 = gelu_exact(v11);
            }
            size_t o0 = (size_t)r0 * Nn + n0 + cl;
            size_t o1 = (size_t)r1 * Nn + n0 + cl;
            if (EPI == EPI_RES) {
                float2 q0 = *(const float2*)(res + o0);
                float2 q1 = *(const float2*)(res + o1);
                v00 += q0.x; v01 += q0.y; v10 += q1.x; v11 += q1.y;
            }
            if (OUTBF16) {
                *(uint32_t*)((__nv_bfloat16*)Cout + o0) = packbf(v00, v01);
                *(uint32_t*)((__nv_bfloat16*)Cout + o1) = packbf(v10, v11);
            } else {
                *(float2*)((float*)Cout + o0) = make_float2(v00, v01);
                *(float2*)((float*)Cout + o1) = make_float2(v10, v11);
            }
        }
    }
}

// ---------------------------------------------------------------------------
// HMMA attention: one block per (window, head), 128 threads (4 warps).
// Scores M=128(pad)xN=104(13 n8)xK=32 in frags; bias+exp2 in regs;
// probs stay in registers as AV A-fragments (no smem round trip).
// smem: Qs/Ks/Vs bf16[128][40] + bias fp32[98][112]
// ---------------------------------------------------------------------------
#define AT_QS 0
#define AT_KS 10240
#define AT_VS 20480
#define AT_BS 30720
#define ASMEM (30720 + 98*112*4)     // 74624

__global__ __launch_bounds__(128)
void attn_hmma(const __nv_bfloat16* __restrict__ qkv, const float* __restrict__ btab,
               __nv_bfloat16* __restrict__ ao) {
    extern __shared__ char smc[];
    __nv_bfloat16* Qs = (__nv_bfloat16*)(smc + AT_QS);
    __nv_bfloat16* Ks = (__nv_bfloat16*)(smc + AT_KS);
    __nv_bfloat16* Vs = (__nv_bfloat16*)(smc + AT_VS);
    float*         bs = (float*)(smc + AT_BS);

    int tid = threadIdx.x, warp = tid >> 5, lane = tid & 31;
    int g = lane >> 2, t4 = lane & 3;
    int win = blockIdx.x >> 2, head = blockIdx.x & 3;
    const float CEXP = 0.17677669529663687f * 1.4426950408889634f;

    // stage q/k/v (rows 98-127 zero), stride 40 bf16
    #pragma unroll
    for (int it = 0; it < 4; it++) {
        int idx = it * 128 + tid;
        int row = idx >> 2, seg = idx & 3;
        uint4 zq = make_uint4(0, 0, 0, 0), zk = zq, zv = zq;
        if (row < 98) {
            const __nv_bfloat16* base = qkv + (size_t)(win * 98 + row) * 384 + head * 32 + seg * 8;
            zq = *(const uint4*)(base);
            zk = *(const uint4*)(base + 128);
            zv = *(const uint4*)(base + 256);
        }
        *(uint4*)(Qs + row * 40 + seg * 8) = zq;
        *(uint4*)(Ks + row * 40 + seg * 8) = zk;
        *(uint4*)(Vs + row * 40 + seg * 8) = zv;
    }
    // stage bias (already * log2e, padded to 112 cols)
    {
        const float4* src = (const float4*)(btab + head * 10976);
        float4* dst = (float4*)bs;
        for (int i = tid; i < 2744; i += 128) dst[i] = src[i];
    }
    __syncthreads();

    uint32_t qAddr = cvta_smem(Qs + (warp * 32 + (lane & 15)) * 40 + (lane >> 4) * 8);
    uint32_t kAddr = cvta_smem(Ks + (lane & 15) * 40 + (lane >> 4) * 8);
    uint32_t vAddr = cvta_smem(Vs + (lane & 15) * 40 + (lane >> 4) * 8);

    // ---- scores: sacc[mi][j][4], j = n8 block 0..12 (cols 0..103) ----
    float sacc[2][13][4];
    #pragma unroll
    for (int mi = 0; mi < 2; mi++)
        #pragma unroll
        for (int j = 0; j < 13; j++)
            #pragma unroll
            for (int q = 0; q < 4; q++) sacc[mi][j][q] = 0.0f;

    #pragma unroll
    for (int ks = 0; ks < 32; ks += 16) {
        uint32_t aF[2][4];
        #pragma unroll
        for (int mi = 0; mi < 2; mi++)
            ldmx4(aF[mi], qAddr + (mi * 16) * 80u + ks * 2u);
        #pragma unroll
        for (int j2 = 0; j2 < 7; j2++) {
            uint32_t r[4];
            ldmx4(r, kAddr + (j2 * 16) * 80u + ks * 2u);
            #pragma unroll
            for (int mi = 0; mi < 2; mi++) {
                mma16816b(sacc[mi][2 * j2], aF[mi], r[0], r[2]);
                if (j2 < 6) mma16816b(sacc[mi][2 * j2 + 1], aF[mi], r[1], r[3]);
            }
        }
    }

    // ---- bias + exp2 + row sums (in registers) ----
    float rsum[2][2] = {{0.0f, 0.0f}, {0.0f, 0.0f}};
    #pragma unroll
    for (int mi = 0; mi < 2; mi++) {
        int ra = warp * 32 + mi * 16 + g;
        int rb = ra + 8;
        bool oka = ra < 98, okb = rb < 98;
        #pragma unroll
        for (int j = 0; j < 13; j++) {
            int c0 = 8 * j + 2 * t4;
            bool cv = c0 < 98;
            float e0 = 0.0f, e1 = 0.0f, e2 = 0.0f, e3 = 0.0f;
            if (cv && oka) {
                float2 bb = *(const float2*)(bs + ra * 112 + c0);
                e0 = exp2f(fmaf(sacc[mi][j][0], CEXP, bb.x));
                e1 = exp2f(fmaf(sacc[mi][j][1], CEXP, bb.y));
            }
            if (cv && okb) {
                float2 bb = *(const float2*)(bs + rb * 112 + c0);
                e2 = exp2f(fmaf(sacc[mi][j][2], CEXP, bb.x));
                e3 = exp2f(fmaf(sacc[mi][j][3], CEXP, bb.y));
            }
            sacc[mi][j][0] = e0; sacc[mi][j][1] = e1;
            sacc[mi][j][2] = e2; sacc[mi][j][3] = e3;
            rsum[mi][0] += e0 + e1;
            rsum[mi][1] += e2 + e3;
        }
    }
    float inv[2][2];
    #pragma unroll
    for (int mi = 0; mi < 2; mi++)
        #pragma unroll
        for (int h2 = 0; h2 < 2; h2++) {
            float r = rsum[mi][h2];
            r += __shfl_xor_sync(0xffffffffu, r, 1);
            r += __shfl_xor_sync(0xffffffffu, r, 2);
            inv[mi][h2] = 1.0f / r;
        }

    // ---- AV: out[128x32] = P[128x112] @ V[112x32], probs from regs ----
    float oacc[2][4][4];
    #pragma unroll
    for (int mi = 0; mi < 2; mi++)
        #pragma unroll
        for (int j = 0; j < 4; j++)
            #pragma unroll
            for (int q = 0; q < 4; q++) oacc[mi][j][q] = 0.0f;

    #pragma unroll
    for (int ks2 = 0; ks2 < 7; ks2++) {
        uint32_t bV[4][2];
        #pragma unroll
        for (int nq = 0; nq < 2; nq++) {
            uint32_t r[4];
            ldmx4t(r, vAddr + (ks2 * 16) * 80u + nq * 32u);
            bV[2 * nq    ][0] = r[0]; bV[2 * nq    ][1] = r[1];
            bV[2 * nq + 1][0] = r[2]; bV[2 * nq + 1][1] = r[3];
        }
        #pragma unroll
        for (int mi = 0; mi < 2; mi++) {
            uint32_t a[4];
            a[0] = packbf(sacc[mi][2 * ks2][0], sacc[mi][2 * ks2][1]);
            a[1] = packbf(sacc[mi][2 * ks2][2], sacc[mi][2 * ks2][3]);
            if (ks2 < 6) {
                a[2] = packbf(sacc[mi][2 * ks2 + 1][0], sacc[mi][2 * ks2 + 1][1]);
                a[3] = packbf(sacc[mi][2 * ks2 + 1][2], sacc[mi][2 * ks2 + 1][3]);
            } else { a[2] = 0u; a[3] = 0u; }
            #pragma unroll
            for (int j = 0; j < 4; j++)
                mma16816(oacc[mi][j], a, bV[j]);
        }
    }

    // ---- scale by 1/rowsum, write bf16 ----
    #pragma unroll
    for (int mi = 0; mi < 2; mi++) {
        int ra = warp * 32 + mi * 16 + g;
        int rb = ra + 8;
        #pragma unroll
        for (int j = 0; j < 4; j++) {
            int c = head * 32 + 8 * j + 2 * t4;
            if (ra < 98)
                *(uint32_t*)(ao + (size_t)(win * 98 + ra) * 128 + c) =
                    packbf(oacc[mi][j][0] * inv[mi][0], oacc[mi][j][1] * inv[mi][0]);
            if (rb < 98)
                *(uint32_t*)(ao + (size_t)(win * 98 + rb) * 128 + c) =
                    packbf(oacc[mi][j][2] * inv[mi][1], oacc[mi][j][3] * inv[mi][1]);
        }
    }
}

// ---------------------------------------------------------------------------
extern "C" void kernel_launch(void* const* d_in, const int* in_sizes, int n_in,
                              void* d_out, int out_size) {
    (void)in_sizes; (void)n_in; (void)out_size;
    const float* x       = (const float*)d_in[0];
    const int*   rel_idx = (const int*)  d_in[1];
    const float* rpb     = (const float*)d_in[2];
    const float* qkv_w   = (const float*)d_in[3];
    const float* qkv_b   = (const float*)d_in[4];
    const float* proj_w  = (const float*)d_in[5];
    const float* proj_b  = (const float*)d_in[6];
    const float* ln1_g   = (const float*)d_in[7];
    const float* ln1_b   = (const float*)d_in[8];
    const float* ln2_g   = (const float*)d_in[9];
    const float* ln2_b   = (const float*)d_in[10];
    const float* mlp_w1  = (const float*)d_in[11];
    const float* mlp_b1  = (const float*)d_in[12];
    const float* mlp_w2  = (const float*)d_in[13];
    const float* mlp_b2  = (const float*)d_in[14];
    float* out = (float*)d_out;

    __nv_bfloat16 *xn, *qkvb, *ao, *xn2, *h1, *wt;
    float *y2, *btab;
    cudaGetSymbolAddress((void**)&xn,   g_xn);
    cudaGetSymbolAddress((void**)&qkvb, g_qkv);
    cudaGetSymbolAddress((void**)&ao,   g_ao);
    cudaGetSymbolAddress((void**)&y2,   g_y2);
    cudaGetSymbolAddress((void**)&xn2,  g_xn2);
    cudaGetSymbolAddress((void**)&h1,   g_h1);
    cudaGetSymbolAddress((void**)&wt,   g_wt);
    cudaGetSymbolAddress((void**)&btab, g_btab);
    __nv_bfloat16* wt_qkv = wt;             // [128][384]
    __nv_bfloat16* wt_prj = wt + 49152;     // [128][128]
    __nv_bfloat16* wt_m1  = wt + 65536;     // [128][512]
    __nv_bfloat16* wt_m2  = wt + 131072;    // [512][128]

    cudaFuncSetAttribute(attn_hmma, cudaFuncAttributeMaxDynamicSharedMemorySize, ASMEM);

    convert_w<<<(128*384 + 255) / 256, 256>>>(qkv_w,  wt_qkv, 128*384);
    convert_w<<<(128*128 + 255) / 256, 256>>>(proj_w, wt_prj, 128*128);
    convert_w<<<(128*512 + 255) / 256, 256>>>(mlp_w1, wt_m1,  128*512);
    convert_w<<<(512*128 + 255) / 256, 256>>>(mlp_w2, wt_m2,  512*128);
    build_bias<<<(4*98*112 + 255) / 256, 256>>>(rel_idx, rpb, btab);

    // 1) LN1 (gathered into window order, bf16)
    ln_bf16<true><<<12544, 256>>>(x, ln1_g, ln1_b, xn);
    // 2) QKV GEMM (bf16 out)
    gemm_hmma<EPI_BIAS, false, true><<<dim3(784, 3), 256>>>(
        xn, wt_qkv, qkv_b, nullptr, qkvb, 384, 128);
    // 3) attention (HMMA)
    attn_hmma<<<4096, 128, ASMEM>>>(qkvb, btab, ao);
    // 4) proj GEMM + residual, scattered to spatial
    gemm_hmma<EPI_RES, true, false><<<dim3(784, 1), 256>>>(
        ao, wt_prj, proj_b, x, y2, 128, 128);
    // 5) LN2
    ln_bf16<false><<<12544, 256>>>(y2, ln2_g, ln2_b, xn2);
    // 6) MLP1 + GELU (bf16 out)
    gemm_hmma<EPI_GELU, false, true><<<dim3(784, 4), 256>>>(
        xn2, wt_m1, mlp_b1, nullptr, h1, 512, 128);
    // 7) MLP2 + residual -> output
    gemm_hmma<EPI_RES, false, false><<<dim3(784, 1), 256>>>(
        h1, wt_m2, mlp_b2, y2, out, 128, 512);
}

// round 6
// speedup vs baseline: 5.1815x; 1.1094x over previous
#include <cuda_runtime.h>
#include <cuda_bf16.h>
#include <math.h>
#include <stdint.h>

// ---------------------------------------------------------------------------
// SwinTransformerBlock3D  (B=4, D=8, H=56, W=56, C=128, WIN=(2,7,7), HEADS=4)
// Fused LN1+QKV, HMMA attention, proj+residual, fused LN2+MLP1+GELU+MLP2+res.
// ---------------------------------------------------------------------------

#define M_TOK 100352            // 4*8*56*56 == 1024 windows * 98 tokens

__device__ __nv_bfloat16 g_qkv[(size_t)M_TOK*384];   // qkv, window order
__device__ __nv_bfloat16 g_ao [(size_t)M_TOK*128];   // attn out, window order
__device__ float         g_y2 [(size_t)M_TOK*128];   // x + proj (spatial)
__device__ __nv_bfloat16 g_wt [196608];              // bf16 weights
__device__ float         g_btab[4*98*112];           // log2e * rpb[rel_idx], padded

// window row r -> spatial token (roll -SHIFT folded in); self-inverse mapping.
__device__ __forceinline__ int win_row_to_token(int r) {
    int win = r / 98;
    int n   = r - win * 98;
    int ww = win & 7;
    int wh = (win >> 3) & 7;
    int wd = (win >> 6) & 3;
    int b  = win >> 8;
    int id  = n / 49;
    int rem = n - id * 49;
    int ih  = rem / 7;
    int iw  = rem - ih * 7;
    int d = wd * 2 + id;
    int h = wh * 7 + ih;
    int w = ww * 7 + iw;
    int ds = d + 1;  if (ds >= 8)  ds -= 8;
    int hs = h + 3;  if (hs >= 56) hs -= 56;
    int ws = w + 3;  if (ws >= 56) ws -= 56;
    return ((b * 8 + ds) * 56 + hs) * 56 + ws;
}

// ---------------------------------------------------------------------------
// helpers
// ---------------------------------------------------------------------------
__device__ __forceinline__ uint32_t cvta_smem(const void* p) {
    uint32_t a;
    asm("{ .reg .u64 t; cvta.to.shared.u64 t, %1; cvt.u32.u64 %0, t; }"
        : "=r"(a) : "l"(p));
    return a;
}
__device__ __forceinline__ uint32_t packbf(float a, float b) {
    __nv_bfloat162 t = __floats2bfloat162_rn(a, b);
    return *reinterpret_cast<uint32_t*>(&t);
}
__device__ __forceinline__ void ldmx4(uint32_t* r, uint32_t addr) {
    asm volatile("ldmatrix.sync.aligned.m8n8.x4.shared.b16 {%0,%1,%2,%3}, [%4];"
        : "=r"(r[0]), "=r"(r[1]), "=r"(r[2]), "=r"(r[3]) : "r"(addr));
}
__device__ __forceinline__ void ldmx4t(uint32_t* r, uint32_t addr) {
    asm volatile("ldmatrix.sync.aligned.m8n8.x4.trans.shared.b16 {%0,%1,%2,%3}, [%4];"
        : "=r"(r[0]), "=r"(r[1]), "=r"(r[2]), "=r"(r[3]) : "r"(addr));
}
__device__ __forceinline__ void mma16816(float* d, const uint32_t* a, const uint32_t* b) {
    asm volatile("mma.sync.aligned.m16n8k16.row.col.f32.bf16.bf16.f32 "
        "{%0,%1,%2,%3}, {%4,%5,%6,%7}, {%8,%9}, {%0,%1,%2,%3};"
        : "+f"(d[0]), "+f"(d[1]), "+f"(d[2]), "+f"(d[3])
        : "r"(a[0]), "r"(a[1]), "r"(a[2]), "r"(a[3]), "r"(b[0]), "r"(b[1]));
}
__device__ __forceinline__ void mma16816b(float* d, const uint32_t* a,
                                          uint32_t b0, uint32_t b1) {
    asm volatile("mma.sync.aligned.m16n8k16.row.col.f32.bf16.bf16.f32 "
        "{%0,%1,%2,%3}, {%4,%5,%6,%7}, {%8,%9}, {%0,%1,%2,%3};"
        : "+f"(d[0]), "+f"(d[1]), "+f"(d[2]), "+f"(d[3])
        : "r"(a[0]), "r"(a[1]), "r"(a[2]), "r"(a[3]), "r"(b0), "r"(b1));
}
__device__ __forceinline__ void cp16(const void* smem_dst, const void* gsrc) {
    uint32_t d = cvta_smem(smem_dst);
    asm volatile("cp.async.cg.shared.global [%0], [%1], 16;" :: "r"(d), "l"(gsrc));
}
#define CP_COMMIT()  asm volatile("cp.async.commit_group;" ::: "memory")
#define CP_WAIT1()   asm volatile("cp.async.wait_group 1;" ::: "memory")
#define CP_WAIT0()   asm volatile("cp.async.wait_group 0;" ::: "memory")
__device__ __forceinline__ float gelu_exact(float v) {
    return 0.5f * v * (1.0f + erff(v * 0.7071067811865476f));
}

// ---------------------------------------------------------------------------
// Single prep kernel: 4 weight casts + bias table
// ---------------------------------------------------------------------------
__global__ void prep_all(const float* __restrict__ qkv_w, const float* __restrict__ proj_w,
                         const float* __restrict__ mlp_w1, const float* __restrict__ mlp_w2,
                         const int* __restrict__ rel_idx, const float* __restrict__ rpb,
                         __nv_bfloat16* __restrict__ wt, float* __restrict__ btab) {
    int i = blockIdx.x * 256 + threadIdx.x;
    if (i < 49152) { wt[i] = __float2bfloat16(qkv_w[i]); return; }
    i -= 49152;
    if (i < 16384) { wt[49152 + i] = __float2bfloat16(proj_w[i]); return; }
    i -= 16384;
    if (i < 65536) { wt[65536 + i] = __float2bfloat16(mlp_w1[i]); return; }
    i -= 65536;
    if (i < 65536) { wt[131072 + i] = __float2bfloat16(mlp_w2[i]); return; }
    i -= 65536;
    if (i < 4 * 98 * 112) {
        int h = i / 10976, rem = i - h * 10976;
        int row = rem / 112, col = rem - row * 112;
        float v = 0.0f;
        if (col < 98) v = rpb[rel_idx[row * 98 + col] * 4 + h] * 1.4426950408889634f;
        btab[i] = v;
    }
}

// ---------------------------------------------------------------------------
// Fused LN1(gather) + QKV GEMM.
// Block: 128 rows (window order). LN -> As bf16 [128][136], then 3 N-chunks
// of 128 with double-buffered weight cp.async. 256 threads, 8 warps (4x2).
// ---------------------------------------------------------------------------
#define LQ_AS 0
#define LQ_BS 34816
#define LQ_SB 104448              // 384 floats
#define LQ_SMEM (104448 + 1536)   // 105984

__global__ __launch_bounds__(256)
void ln_qkv(const float* __restrict__ x, const float* __restrict__ g,
            const float* __restrict__ beta, const __nv_bfloat16* __restrict__ W,
            const float* __restrict__ bias, __nv_bfloat16* __restrict__ qkv) {
    extern __shared__ char smc[];
    __nv_bfloat16* As = (__nv_bfloat16*)(smc + LQ_AS);
    __nv_bfloat16* Bs = (__nv_bfloat16*)(smc + LQ_BS);
    float*         sb = (float*)(smc + LQ_SB);

    int tid = threadIdx.x, lane = tid & 31, wid = tid >> 5;
    int wm = wid & 3, wn = wid >> 2;
    int m0 = blockIdx.x * 128;

    // prefetch W chunk 0
    #pragma unroll
    for (int it = 0; it < 8; it++) {
        int idx = it * 256 + tid;
        int row = idx >> 4, seg = idx & 15;
        cp16(Bs + row * 136 + seg * 8, W + row * 384 + seg * 8);
    }
    CP_COMMIT();
    for (int i = tid; i < 384; i += 256) sb[i] = bias[i];

    // LN (gathered rows) -> As
    #pragma unroll
    for (int i = 0; i < 16; i++) {
        int r = i * 8 + wid;
        int src = win_row_to_token(m0 + r);
        float4 v = *(const float4*)(x + (size_t)src * 128 + lane * 4);
        float s  = v.x + v.y + v.z + v.w;
        float s2 = fmaf(v.x, v.x, fmaf(v.y, v.y, fmaf(v.z, v.z, v.w * v.w)));
        #pragma unroll
        for (int o = 16; o; o >>= 1) {
            s  += __shfl_xor_sync(0xffffffffu, s,  o);
            s2 += __shfl_xor_sync(0xffffffffu, s2, o);
        }
        float mu  = s * (1.0f / 128.0f);
        float var = s2 * (1.0f / 128.0f) - mu * mu;
        float inv = rsqrtf(var + 1e-5f);
        float4 gv = *(const float4*)(g + lane * 4);
        float4 bv = *(const float4*)(beta + lane * 4);
        uint2 u;
        u.x = packbf((v.x - mu) * inv * gv.x + bv.x, (v.y - mu) * inv * gv.y + bv.y);
        u.y = packbf((v.z - mu) * inv * gv.z + bv.z, (v.w - mu) * inv * gv.w + bv.w);
        *(uint2*)(As + r * 136 + lane * 4) = u;
    }

    uint32_t aAddr = cvta_smem(As + (wm * 32 + (lane & 15)) * 136 + (lane >> 4) * 8);
    uint32_t bAddr0 = cvta_smem(Bs + (lane & 15) * 136 + wn * 64 + (lane >> 4) * 8);
    int gcol = lane >> 2, t4 = lane & 3;

    for (int c = 0; c < 3; c++) {
        CP_WAIT0();
        __syncthreads();
        if (c < 2) {
            __nv_bfloat16* dst = Bs + ((c + 1) & 1) * 17408;
            const __nv_bfloat16* src = W + (c + 1) * 128;
            #pragma unroll
            for (int it = 0; it < 8; it++) {
                int idx = it * 256 + tid;
                int row = idx >> 4, seg = idx & 15;
                cp16(dst + row * 136 + seg * 8, src + row * 384 + seg * 8);
            }
            CP_COMMIT();
        }

        float acc[2][8][4];
        #pragma unroll
        for (int mi = 0; mi < 2; mi++)
            #pragma unroll
            for (int ni = 0; ni < 8; ni++)
                #pragma unroll
                for (int q = 0; q < 4; q++) acc[mi][ni][q] = 0.0f;

        uint32_t bAddr = bAddr0 + (c & 1) * 34816u;
        #pragma unroll
        for (int s = 0; s < 8; s++) {
            uint32_t aF[2][4];
            #pragma unroll
            for (int mi = 0; mi < 2; mi++)
                ldmx4(aF[mi], aAddr + mi * 4352u + s * 32u);
            uint32_t bF[8][2];
            #pragma unroll
            for (int np = 0; np < 4; np++) {
                uint32_t r[4];
                ldmx4t(r, bAddr + s * 4352u + np * 32u);
                bF[2 * np    ][0] = r[0]; bF[2 * np    ][1] = r[1];
                bF[2 * np + 1][0] = r[2]; bF[2 * np + 1][1] = r[3];
            }
            #pragma unroll
            for (int mi = 0; mi < 2; mi++)
                #pragma unroll
                for (int ni = 0; ni < 8; ni++)
                    mma16816(acc[mi][ni], aF[mi], bF[ni]);
        }

        #pragma unroll
        for (int mi = 0; mi < 2; mi++) {
            int rl = wm * 32 + mi * 16 + gcol;
            #pragma unroll
            for (int ni = 0; ni < 8; ni++) {
                int cl = wn * 64 + ni * 8 + t4 * 2;
                float b0 = sb[c * 128 + cl], b1 = sb[c * 128 + cl + 1];
                *(uint32_t*)(qkv + (size_t)(m0 + rl) * 384 + c * 128 + cl) =
                    packbf(acc[mi][ni][0] + b0, acc[mi][ni][1] + b1);
                *(uint32_t*)(qkv + (size_t)(m0 + rl + 8) * 384 + c * 128 + cl) =
                    packbf(acc[mi][ni][2] + b0, acc[mi][ni][3] + b1);
            }
        }
        __syncthreads();
    }
}

// ---------------------------------------------------------------------------
// HMMA attention: one block per (window, head), 256 threads (8 warps x 16 rows).
// Bias read straight from L2-resident table. smem: Q/K/V bf16 [128][40].
// ---------------------------------------------------------------------------
#define ASMEM 30720

__global__ __launch_bounds__(256)
void attn_hmma(const __nv_bfloat16* __restrict__ qkv, const float* __restrict__ btab,
               __nv_bfloat16* __restrict__ ao) {
    extern __shared__ char smc[];
    __nv_bfloat16* Qs = (__nv_bfloat16*)(smc);
    __nv_bfloat16* Ks = (__nv_bfloat16*)(smc + 10240);
    __nv_bfloat16* Vs = (__nv_bfloat16*)(smc + 20480);

    int tid = threadIdx.x, warp = tid >> 5, lane = tid & 31;
    int g = lane >> 2, t4 = lane & 3;
    int win = blockIdx.x >> 2, head = blockIdx.x & 3;
    const float CEXP = 0.17677669529663687f * 1.4426950408889634f;
    const float* bt = btab + head * 10976;

    #pragma unroll
    for (int it = 0; it < 2; it++) {
        int idx = it * 256 + tid;
        int row = idx >> 2, seg = idx & 3;
        uint4 zq = make_uint4(0, 0, 0, 0), zk = zq, zv = zq;
        if (row < 98) {
            const __nv_bfloat16* base = qkv + (size_t)(win * 98 + row) * 384 + head * 32 + seg * 8;
            zq = *(const uint4*)(base);
            zk = *(const uint4*)(base + 128);
            zv = *(const uint4*)(base + 256);
        }
        *(uint4*)(Qs + row * 40 + seg * 8) = zq;
        *(uint4*)(Ks + row * 40 + seg * 8) = zk;
        *(uint4*)(Vs + row * 40 + seg * 8) = zv;
    }
    __syncthreads();

    uint32_t qAddr = cvta_smem(Qs + (warp * 16 + (lane & 15)) * 40 + (lane >> 4) * 8);
    uint32_t kAddr = cvta_smem(Ks + (lane & 15) * 40 + (lane >> 4) * 8);
    uint32_t vAddr = cvta_smem(Vs + (lane & 15) * 40 + (lane >> 4) * 8);

    // scores (16 rows x 104 cols per warp)
    float sacc[13][4];
    #pragma unroll
    for (int j = 0; j < 13; j++)
        #pragma unroll
        for (int q = 0; q < 4; q++) sacc[j][q] = 0.0f;

    #pragma unroll
    for (int ks = 0; ks < 32; ks += 16) {
        uint32_t aF[4];
        ldmx4(aF, qAddr + ks * 2u);
        #pragma unroll
        for (int j2 = 0; j2 < 7; j2++) {
            uint32_t r[4];
            ldmx4(r, kAddr + j2 * 1280u + ks * 2u);
            mma16816b(sacc[2 * j2], aF, r[0], r[2]);
            if (j2 < 6) mma16816b(sacc[2 * j2 + 1], aF, r[1], r[3]);
        }
    }

    // bias + exp2 + row sums
    int ra = warp * 16 + g, rb = ra + 8;
    bool oka = ra < 98, okb = rb < 98;
    float rsum0 = 0.0f, rsum1 = 0.0f;
    #pragma unroll
    for (int j = 0; j < 13; j++) {
        int c0 = 8 * j + 2 * t4;
        bool cv = c0 < 98;
        float e0 = 0.0f, e1 = 0.0f, e2 = 0.0f, e3 = 0.0f;
        if (cv && oka) {
            float2 bb = *(const float2*)(bt + ra * 112 + c0);
            e0 = exp2f(fmaf(sacc[j][0], CEXP, bb.x));
            e1 = exp2f(fmaf(sacc[j][1], CEXP, bb.y));
        }
        if (cv && okb) {
            float2 bb = *(const float2*)(bt + rb * 112 + c0);
            e2 = exp2f(fmaf(sacc[j][2], CEXP, bb.x));
            e3 = exp2f(fmaf(sacc[j][3], CEXP, bb.y));
        }
        sacc[j][0] = e0; sacc[j][1] = e1; sacc[j][2] = e2; sacc[j][3] = e3;
        rsum0 += e0 + e1;
        rsum1 += e2 + e3;
    }
    rsum0 += __shfl_xor_sync(0xffffffffu, rsum0, 1);
    rsum0 += __shfl_xor_sync(0xffffffffu, rsum0, 2);
    rsum1 += __shfl_xor_sync(0xffffffffu, rsum1, 1);
    rsum1 += __shfl_xor_sync(0xffffffffu, rsum1, 2);
    float inv0 = 1.0f / rsum0, inv1 = 1.0f / rsum1;

    // AV
    float oacc[4][4];
    #pragma unroll
    for (int j = 0; j < 4; j++)
        #pragma unroll
        for (int q = 0; q < 4; q++) oacc[j][q] = 0.0f;

    #pragma unroll
    for (int ks2 = 0; ks2 < 7; ks2++) {
        uint32_t bV[4][2];
        #pragma unroll
        for (int nq = 0; nq < 2; nq++) {
            uint32_t r[4];
            ldmx4t(r, vAddr + ks2 * 1280u + nq * 32u);
            bV[2 * nq    ][0] = r[0]; bV[2 * nq    ][1] = r[1];
            bV[2 * nq + 1][0] = r[2]; bV[2 * nq + 1][1] = r[3];
        }
        uint32_t a[4];
        a[0] = packbf(sacc[2 * ks2][0], sacc[2 * ks2][1]);
        a[1] = packbf(sacc[2 * ks2][2], sacc[2 * ks2][3]);
        if (ks2 < 6) {
            a[2] = packbf(sacc[2 * ks2 + 1][0], sacc[2 * ks2 + 1][1]);
            a[3] = packbf(sacc[2 * ks2 + 1][2], sacc[2 * ks2 + 1][3]);
        } else { a[2] = 0u; a[3] = 0u; }
        #pragma unroll
        for (int j = 0; j < 4; j++)
            mma16816(oacc[j], a, bV[j]);
    }

    #pragma unroll
    for (int j = 0; j < 4; j++) {
        int c = head * 32 + 8 * j + 2 * t4;
        if (oka)
            *(uint32_t*)(ao + (size_t)(win * 98 + ra) * 128 + c) =
                packbf(oacc[j][0] * inv0, oacc[j][1] * inv0);
        if (okb)
            *(uint32_t*)(ao + (size_t)(win * 98 + rb) * 128 + c) =
                packbf(oacc[j][2] * inv1, oacc[j][3] * inv1);
    }
}

// ---------------------------------------------------------------------------
// Proj GEMM + residual, scatter rows to spatial layout (from round 4).
// ---------------------------------------------------------------------------
__global__ __launch_bounds__(256)
void gemm_proj(const __nv_bfloat16* __restrict__ A, const __nv_bfloat16* __restrict__ W,
               const float* __restrict__ bias, const float* __restrict__ res,
               float* __restrict__ Cout) {
    __shared__ __nv_bfloat16 As[2][128][40];
    __shared__ __nv_bfloat16 Bs[2][32][136];
    __shared__ int   rowmap[128];
    __shared__ float sbias[128];

    const int Nn = 128, K = 128;
    int tid = threadIdx.x, lane = tid & 31, wid = tid >> 5;
    int wm = wid & 3, wn = wid >> 2;
    int m0 = blockIdx.x * 128;

    if (tid < 128) {
        sbias[tid] = bias[tid];
        rowmap[tid] = win_row_to_token(m0 + tid);
    }

    int arow = tid >> 2, aseg = tid & 3;
    int brow = tid >> 4, bseg = tid & 15;

    float acc[2][8][4];
    #pragma unroll
    for (int mi = 0; mi < 2; mi++)
        #pragma unroll
        for (int ni = 0; ni < 8; ni++)
            #pragma unroll
            for (int q = 0; q < 4; q++) acc[mi][ni][q] = 0.0f;

    uint32_t aAddr = cvta_smem(&As[0][wm * 32 + (lane & 15)][(lane >> 4) * 8]);
    uint32_t bAddr = cvta_smem(&Bs[0][(lane & 15)][wn * 64 + (lane >> 4) * 8]);

    #pragma unroll
    for (int i = 0; i < 2; i++)
        cp16(&As[0][arow + i * 64][aseg * 8], A + (size_t)(m0 + arow + i * 64) * K + aseg * 8);
    #pragma unroll
    for (int i = 0; i < 2; i++)
        cp16(&Bs[0][brow + i * 16][bseg * 8], W + (size_t)(brow + i * 16) * Nn + bseg * 8);
    CP_COMMIT();

    const int nk = 4;
    for (int c = 0; c < nk; c++) {
        if (c + 1 < nk) {
            int kc = (c + 1) << 5, s = (c + 1) & 1;
            #pragma unroll
            for (int i = 0; i < 2; i++)
                cp16(&As[s][arow + i * 64][aseg * 8],
                     A + (size_t)(m0 + arow + i * 64) * K + kc + aseg * 8);
            #pragma unroll
            for (int i = 0; i < 2; i++)
                cp16(&Bs[s][brow + i * 16][bseg * 8],
                     W + (size_t)(kc + brow + i * 16) * Nn + bseg * 8);
        }
        CP_COMMIT();
        CP_WAIT1();
        __syncthreads();

        uint32_t aOff = aAddr + (c & 1) * 10240u;
        uint32_t bOff = bAddr + (c & 1) * 8704u;
        #pragma unroll
        for (int ks = 0; ks < 32; ks += 16) {
            uint32_t aF[2][4];
            #pragma unroll
            for (int mi = 0; mi < 2; mi++)
                ldmx4(aF[mi], aOff + (mi * 16) * 80u + ks * 2u);
            uint32_t bF[8][2];
            #pragma unroll
            for (int np = 0; np < 4; np++) {
                uint32_t r[4];
                ldmx4t(r, bOff + ks * 272u + np * 32u);
                bF[2 * np    ][0] = r[0]; bF[2 * np    ][1] = r[1];
                bF[2 * np + 1][0] = r[2]; bF[2 * np + 1][1] = r[3];
            }
            #pragma unroll
            for (int mi = 0; mi < 2; mi++)
                #pragma unroll
                for (int ni = 0; ni < 8; ni++)
                    mma16816(acc[mi][ni], aF[mi], bF[ni]);
        }
        __syncthreads();
    }

    int g = lane >> 2, t4 = lane & 3;
    #pragma unroll
    for (int mi = 0; mi < 2; mi++) {
        int rl = wm * 32 + mi * 16 + g;
        int r0 = rowmap[rl], r1 = rowmap[rl + 8];
        #pragma unroll
        for (int ni = 0; ni < 8; ni++) {
            int cl = wn * 64 + ni * 8 + t4 * 2;
            float b0 = sbias[cl], b1 = sbias[cl + 1];
            size_t o0 = (size_t)r0 * Nn + cl;
            size_t o1 = (size_t)r1 * Nn + cl;
            float2 q0 = *(const float2*)(res + o0);
            float2 q1 = *(const float2*)(res + o1);
            *(float2*)(Cout + o0) = make_float2(acc[mi][ni][0] + b0 + q0.x,
                                                acc[mi][ni][1] + b1 + q0.y);
            *(float2*)(Cout + o1) = make_float2(acc[mi][ni][2] + b0 + q1.x,
                                                acc[mi][ni][3] + b1 + q1.y);
        }
    }
}

// ---------------------------------------------------------------------------
// Fused LN2 + MLP1 + GELU + MLP2 + residual.
// Block: 128 rows. LN -> As; loop 4 chunks: H = gelu(A@W1c + b1) -> Hs;
// oacc += H@W2c. Epilogue: +b2 +y2 -> out (fp32).
// ---------------------------------------------------------------------------
#define FM_AS 0
#define FM_HS 34816
#define FM_W1 69632                  // 2 x 34816
#define FM_W2 139264                 // 2 x 34816
#define FM_B1 208896                 // 512 floats
#define FM_B2 210944                 // 128 floats
#define FM_SMEM 211456

__global__ __launch_bounds__(256)
void fused_mlp(const float* __restrict__ y2, const float* __restrict__ g,
               const float* __restrict__ beta, const __nv_bfloat16* __restrict__ W1,
               const float* __restrict__ b1, const __nv_bfloat16* __restrict__ W2,
               const float* __restrict__ b2, float* __restrict__ out) {
    extern __shared__ char smc[];
    __nv_bfloat16* As  = (__nv_bfloat16*)(smc + FM_AS);
    __nv_bfloat16* Hs  = (__nv_bfloat16*)(smc + FM_HS);
    __nv_bfloat16* W1s = (__nv_bfloat16*)(smc + FM_W1);
    __nv_bfloat16* W2s = (__nv_bfloat16*)(smc + FM_W2);
    float* sb1 = (float*)(smc + FM_B1);
    float* sb2 = (float*)(smc + FM_B2);

    int tid = threadIdx.x, lane = tid & 31, wid = tid >> 5;
    int wm = wid & 3, wn = wid >> 2;
    int m0 = blockIdx.x * 128;

    // prefetch chunk 0 of W1, W2
    #pragma unroll
    for (int it = 0; it < 8; it++) {
        int idx = it * 256 + tid;
        int row = idx >> 4, seg = idx & 15;
        cp16(W1s + row * 136 + seg * 8, W1 + row * 512 + seg * 8);
        cp16(W2s + row * 136 + seg * 8, W2 + row * 128 + seg * 8);
    }
    CP_COMMIT();
    for (int i = tid; i < 512; i += 256) sb1[i] = b1[i];
    if (tid < 128) sb2[tid] = b2[tid];

    // LN2 -> As
    #pragma unroll
    for (int i = 0; i < 16; i++) {
        int r = i * 8 + wid;
        float4 v = *(const float4*)(y2 + (size_t)(m0 + r) * 128 + lane * 4);
        float s  = v.x + v.y + v.z + v.w;
        float s2 = fmaf(v.x, v.x, fmaf(v.y, v.y, fmaf(v.z, v.z, v.w * v.w)));
        #pragma unroll
        for (int o = 16; o; o >>= 1) {
            s  += __shfl_xor_sync(0xffffffffu, s,  o);
            s2 += __shfl_xor_sync(0xffffffffu, s2, o);
        }
        float mu  = s * (1.0f / 128.0f);
        float var = s2 * (1.0f / 128.0f) - mu * mu;
        float inv = rsqrtf(var + 1e-5f);
        float4 gv = *(const float4*)(g + lane * 4);
        float4 bv = *(const float4*)(beta + lane * 4);
        uint2 u;
        u.x = packbf((v.x - mu) * inv * gv.x + bv.x, (v.y - mu) * inv * gv.y + bv.y);
        u.y = packbf((v.z - mu) * inv * gv.z + bv.z, (v.w - mu) * inv * gv.w + bv.w);
        *(uint2*)(As + r * 136 + lane * 4) = u;
    }

    uint32_t aAddr  = cvta_smem(As + (wm * 32 + (lane & 15)) * 136 + (lane >> 4) * 8);
    uint32_t hAddrW = cvta_smem(Hs + (wm * 32 + (lane & 15)) * 136 + (lane >> 4) * 8);
    uint32_t w1Addr0 = cvta_smem(W1s + (lane & 15) * 136 + wn * 64 + (lane >> 4) * 8);
    uint32_t w2Addr0 = cvta_smem(W2s + (lane & 15) * 136 + wn * 64 + (lane >> 4) * 8);
    int gcol = lane >> 2, t4 = lane & 3;

    float oacc[2][8][4];
    #pragma unroll
    for (int mi = 0; mi < 2; mi++)
        #pragma unroll
        for (int ni = 0; ni < 8; ni++)
            #pragma unroll
            for (int q = 0; q < 4; q++) oacc[mi][ni][q] = 0.0f;

    for (int c = 0; c < 4; c++) {
        CP_WAIT0();
        __syncthreads();
        if (c < 3) {
            __nv_bfloat16* d1 = W1s + ((c + 1) & 1) * 17408;
            __nv_bfloat16* d2 = W2s + ((c + 1) & 1) * 17408;
            const __nv_bfloat16* s1 = W1 + (c + 1) * 128;
            const __nv_bfloat16* s2 = W2 + (size_t)(c + 1) * 128 * 128;
            #pragma unroll
            for (int it = 0; it < 8; it++) {
                int idx = it * 256 + tid;
                int row = idx >> 4, seg = idx & 15;
                cp16(d1 + row * 136 + seg * 8, s1 + row * 512 + seg * 8);
                cp16(d2 + row * 136 + seg * 8, s2 + row * 128 + seg * 8);
            }
            CP_COMMIT();
        }

        // H = A @ W1c
        float hacc[2][8][4];
        #pragma unroll
        for (int mi = 0; mi < 2; mi++)
            #pragma unroll
            for (int ni = 0; ni < 8; ni++)
                #pragma unroll
                for (int q = 0; q < 4; q++) hacc[mi][ni][q] = 0.0f;

        uint32_t w1Addr = w1Addr0 + (c & 1) * 34816u;
        #pragma unroll
        for (int s = 0; s < 8; s++) {
            uint32_t aF[2][4];
            #pragma unroll
            for (int mi = 0; mi < 2; mi++)
                ldmx4(aF[mi], aAddr + mi * 4352u + s * 32u);
            uint32_t bF[8][2];
            #pragma unroll
            for (int np = 0; np < 4; np++) {
                uint32_t r[4];
                ldmx4t(r, w1Addr + s * 4352u + np * 32u);
                bF[2 * np    ][0] = r[0]; bF[2 * np    ][1] = r[1];
                bF[2 * np + 1][0] = r[2]; bF[2 * np + 1][1] = r[3];
            }
            #pragma unroll
            for (int mi = 0; mi < 2; mi++)
                #pragma unroll
                for (int ni = 0; ni < 8; ni++)
                    mma16816(hacc[mi][ni], aF[mi], bF[ni]);
        }

        // gelu + pack -> Hs
        #pragma unroll
        for (int mi = 0; mi < 2; mi++) {
            int rl = wm * 32 + mi * 16 + gcol;
            #pragma unroll
            for (int ni = 0; ni < 8; ni++) {
                int cl = wn * 64 + ni * 8 + t4 * 2;
                float b0 = sb1[c * 128 + cl], b1v = sb1[c * 128 + cl + 1];
                *(uint32_t*)(Hs + rl * 136 + cl) =
                    packbf(gelu_exact(hacc[mi][ni][0] + b0), gelu_exact(hacc[mi][ni][1] + b1v));
                *(uint32_t*)(Hs + (rl + 8) * 136 + cl) =
                    packbf(gelu_exact(hacc[mi][ni][2] + b0), gelu_exact(hacc[mi][ni][3] + b1v));
            }
        }
        __syncthreads();

        // oacc += H @ W2c
        uint32_t w2Addr = w2Addr0 + (c & 1) * 34816u;
        #pragma unroll
        for (int s = 0; s < 8; s++) {
            uint32_t aF[2][4];
            #pragma unroll
            for (int mi = 0; mi < 2; mi++)
                ldmx4(aF[mi], hAddrW + mi * 4352u + s * 32u);
            uint32_t bF[8][2];
            #pragma unroll
            for (int np = 0; np < 4; np++) {
                uint32_t r[4];
                ldmx4t(r, w2Addr + s * 4352u + np * 32u);
                bF[2 * np    ][0] = r[0]; bF[2 * np    ][1] = r[1];
                bF[2 * np + 1][0] = r[2]; bF[2 * np + 1][1] = r[3];
            }
            #pragma unroll
            for (int mi = 0; mi < 2; mi++)
                #pragma unroll
                for (int ni = 0; ni < 8; ni++)
                    mma16816(oacc[mi][ni], aF[mi], bF[ni]);
        }
    }

    // epilogue: +b2 + residual y2 -> out fp32
    #pragma unroll
    for (int mi = 0; mi < 2; mi++) {
        int rl = wm * 32 + mi * 16 + gcol;
        #pragma unroll
        for (int ni = 0; ni < 8; ni++) {
            int cl = wn * 64 + ni * 8 + t4 * 2;
            float b0 = sb2[cl], b1v = sb2[cl + 1];
            size_t o0 = (size_t)(m0 + rl) * 128 + cl;
            size_t o1 = (size_t)(m0 + rl + 8) * 128 + cl;
            float2 q0 = *(const float2*)(y2 + o0);
            float2 q1 = *(const float2*)(y2 + o1);
            *(float2*)(out + o0) = make_float2(oacc[mi][ni][0] + b0 + q0.x,
                                               oacc[mi][ni][1] + b1v + q0.y);
            *(float2*)(out + o1) = make_float2(oacc[mi][ni][2] + b0 + q1.x,
                                               oacc[mi][ni][3] + b1v + q1.y);
        }
    }
}

// ---------------------------------------------------------------------------
extern "C" void kernel_launch(void* const* d_in, const int* in_sizes, int n_in,
                              void* d_out, int out_size) {
    (void)in_sizes; (void)n_in; (void)out_size;
    const float* x       = (const float*)d_in[0];
    const int*   rel_idx = (const int*)  d_in[1];
    const float* rpb     = (const float*)d_in[2];
    const float* qkv_w   = (const float*)d_in[3];
    const float* qkv_b   = (const float*)d_in[4];
    const float* proj_w  = (const float*)d_in[5];
    const float* proj_b  = (const float*)d_in[6];
    const float* ln1_g   = (const float*)d_in[7];
    const float* ln1_b   = (const float*)d_in[8];
    const float* ln2_g   = (const float*)d_in[9];
    const float* ln2_b   = (const float*)d_in[10];
    const float* mlp_w1  = (const float*)d_in[11];
    const float* mlp_b1  = (const float*)d_in[12];
    const float* mlp_w2  = (const float*)d_in[13];
    const float* mlp_b2  = (const float*)d_in[14];
    float* out = (float*)d_out;

    __nv_bfloat16 *qkvb, *ao, *wt;
    float *y2, *btab;
    cudaGetSymbolAddress((void**)&qkvb, g_qkv);
    cudaGetSymbolAddress((void**)&ao,   g_ao);
    cudaGetSymbolAddress((void**)&y2,   g_y2);
    cudaGetSymbolAddress((void**)&wt,   g_wt);
    cudaGetSymbolAddress((void**)&btab, g_btab);
    __nv_bfloat16* wt_qkv = wt;             // [128][384]
    __nv_bfloat16* wt_prj = wt + 49152;     // [128][128]
    __nv_bfloat16* wt_m1  = wt + 65536;     // [128][512]
    __nv_bfloat16* wt_m2  = wt + 131072;    // [512][128]

    cudaFuncSetAttribute(ln_qkv,    cudaFuncAttributeMaxDynamicSharedMemorySize, LQ_SMEM);
    cudaFuncSetAttribute(attn_hmma, cudaFuncAttributeMaxDynamicSharedMemorySize, ASMEM);
    cudaFuncSetAttribute(fused_mlp, cudaFuncAttributeMaxDynamicSharedMemorySize, FM_SMEM);

    prep_all<<<940, 256>>>(qkv_w, proj_w, mlp_w1, mlp_w2, rel_idx, rpb, wt, btab);
    ln_qkv<<<784, 256, LQ_SMEM>>>(x, ln1_g, ln1_b, wt_qkv, qkv_b, qkvb);
    attn_hmma<<<4096, 256, ASMEM>>>(qkvb, btab, ao);
    gemm_proj<<<784, 256>>>(ao, wt_prj, proj_b, x, y2);
    fused_mlp<<<784, 256, FM_SMEM>>>(y2, ln2_g, ln2_b, wt_m1, mlp_b1, wt_m2, mlp_b2, out);
}

// round 7
// speedup vs baseline: 5.2607x; 1.0153x over previous
#include <cuda_runtime.h>
#include <cuda_bf16.h>
#include <math.h>
#include <stdint.h>

// ---------------------------------------------------------------------------
// SwinTransformerBlock3D  (B=4, D=8, H=56, W=56, C=128, WIN=(2,7,7), HEADS=4)
// 512-thread HMMA kernels (32x32 warp tiles): fused LN1+QKV, HMMA attention,
// proj+residual, fused LN2+MLP1+GELU+MLP2+residual.
// ---------------------------------------------------------------------------

#define M_TOK 100352            // 4*8*56*56 == 1024 windows * 98 tokens

__device__ __nv_bfloat16 g_qkv[(size_t)M_TOK*384];   // qkv, window order
__device__ __nv_bfloat16 g_ao [(size_t)M_TOK*128];   // attn out, window order
__device__ float         g_y2 [(size_t)M_TOK*128];   // x + proj (spatial)
__device__ __nv_bfloat16 g_wt [196608];              // bf16 weights
__device__ float         g_btab[4*98*112];           // log2e * rpb[rel_idx], padded

// window row r -> spatial token (roll -SHIFT folded in); self-inverse mapping.
__device__ __forceinline__ int win_row_to_token(int r) {
    int win = r / 98;
    int n   = r - win * 98;
    int ww = win & 7;
    int wh = (win >> 3) & 7;
    int wd = (win >> 6) & 3;
    int b  = win >> 8;
    int id  = n / 49;
    int rem = n - id * 49;
    int ih  = rem / 7;
    int iw  = rem - ih * 7;
    int d = wd * 2 + id;
    int h = wh * 7 + ih;
    int w = ww * 7 + iw;
    int ds = d + 1;  if (ds >= 8)  ds -= 8;
    int hs = h + 3;  if (hs >= 56) hs -= 56;
    int ws = w + 3;  if (ws >= 56) ws -= 56;
    return ((b * 8 + ds) * 56 + hs) * 56 + ws;
}

// ---------------------------------------------------------------------------
// helpers
// ---------------------------------------------------------------------------
__device__ __forceinline__ uint32_t cvta_smem(const void* p) {
    uint32_t a;
    asm("{ .reg .u64 t; cvta.to.shared.u64 t, %1; cvt.u32.u64 %0, t; }"
        : "=r"(a) : "l"(p));
    return a;
}
__device__ __forceinline__ uint32_t packbf(float a, float b) {
    __nv_bfloat162 t = __floats2bfloat162_rn(a, b);
    return *reinterpret_cast<uint32_t*>(&t);
}
__device__ __forceinline__ void ldmx4(uint32_t* r, uint32_t addr) {
    asm volatile("ldmatrix.sync.aligned.m8n8.x4.shared.b16 {%0,%1,%2,%3}, [%4];"
        : "=r"(r[0]), "=r"(r[1]), "=r"(r[2]), "=r"(r[3]) : "r"(addr));
}
__device__ __forceinline__ void ldmx4t(uint32_t* r, uint32_t addr) {
    asm volatile("ldmatrix.sync.aligned.m8n8.x4.trans.shared.b16 {%0,%1,%2,%3}, [%4];"
        : "=r"(r[0]), "=r"(r[1]), "=r"(r[2]), "=r"(r[3]) : "r"(addr));
}
__device__ __forceinline__ void mma16816(float* d, const uint32_t* a, const uint32_t* b) {
    asm volatile("mma.sync.aligned.m16n8k16.row.col.f32.bf16.bf16.f32 "
        "{%0,%1,%2,%3}, {%4,%5,%6,%7}, {%8,%9}, {%0,%1,%2,%3};"
        : "+f"(d[0]), "+f"(d[1]), "+f"(d[2]), "+f"(d[3])
        : "r"(a[0]), "r"(a[1]), "r"(a[2]), "r"(a[3]), "r"(b[0]), "r"(b[1]));
}
__device__ __forceinline__ void mma16816b(float* d, const uint32_t* a,
                                          uint32_t b0, uint32_t b1) {
    asm volatile("mma.sync.aligned.m16n8k16.row.col.f32.bf16.bf16.f32 "
        "{%0,%1,%2,%3}, {%4,%5,%6,%7}, {%8,%9}, {%0,%1,%2,%3};"
        : "+f"(d[0]), "+f"(d[1]), "+f"(d[2]), "+f"(d[3])
        : "r"(a[0]), "r"(a[1]), "r"(a[2]), "r"(a[3]), "r"(b0), "r"(b1));
}
__device__ __forceinline__ void cp16(const void* smem_dst, const void* gsrc) {
    uint32_t d = cvta_smem(smem_dst);
    asm volatile("cp.async.cg.shared.global [%0], [%1], 16;" :: "r"(d), "l"(gsrc));
}
#define CP_COMMIT()  asm volatile("cp.async.commit_group;" ::: "memory")
#define CP_WAIT0()   asm volatile("cp.async.wait_group 0;" ::: "memory")
__device__ __forceinline__ float gelu_exact(float v) {
    return 0.5f * v * (1.0f + erff(v * 0.7071067811865476f));
}

// ---------------------------------------------------------------------------
// Single prep kernel: 4 weight casts + bias table
// ---------------------------------------------------------------------------
__global__ void prep_all(const float* __restrict__ qkv_w, const float* __restrict__ proj_w,
                         const float* __restrict__ mlp_w1, const float* __restrict__ mlp_w2,
                         const int* __restrict__ rel_idx, const float* __restrict__ rpb,
                         __nv_bfloat16* __restrict__ wt, float* __restrict__ btab) {
    int i = blockIdx.x * 256 + threadIdx.x;
    if (i < 49152) { wt[i] = __float2bfloat16(qkv_w[i]); return; }
    i -= 49152;
    if (i < 16384) { wt[49152 + i] = __float2bfloat16(proj_w[i]); return; }
    i -= 16384;
    if (i < 65536) { wt[65536 + i] = __float2bfloat16(mlp_w1[i]); return; }
    i -= 65536;
    if (i < 65536) { wt[131072 + i] = __float2bfloat16(mlp_w2[i]); return; }
    i -= 65536;
    if (i < 4 * 98 * 112) {
        int h = i / 10976, rem = i - h * 10976;
        int row = rem / 112, col = rem - row * 112;
        float v = 0.0f;
        if (col < 98) v = rpb[rel_idx[row * 98 + col] * 4 + h] * 1.4426950408889634f;
        btab[i] = v;
    }
}

// ---------------------------------------------------------------------------
// Fused LN1(gather) + QKV GEMM. 512 threads, 16 warps (4x4, 32x32 tiles).
// ---------------------------------------------------------------------------
#define LQ_AS 0
#define LQ_BS 34816
#define LQ_SB 104448              // 384 floats
#define LQ_SMEM (104448 + 1536)   // 105984

__global__ __launch_bounds__(512, 2)
void ln_qkv(const float* __restrict__ x, const float* __restrict__ g,
            const float* __restrict__ beta, const __nv_bfloat16* __restrict__ W,
            const float* __restrict__ bias, __nv_bfloat16* __restrict__ qkv) {
    extern __shared__ char smc[];
    __nv_bfloat16* As = (__nv_bfloat16*)(smc + LQ_AS);
    __nv_bfloat16* Bs = (__nv_bfloat16*)(smc + LQ_BS);
    float*         sb = (float*)(smc + LQ_SB);

    int tid = threadIdx.x, lane = tid & 31, wid = tid >> 5;
    int wm = wid & 3, wn = wid >> 2;
    int m0 = blockIdx.x * 128;

    // prefetch W chunk 0 (128 rows x 16 segs)
    #pragma unroll
    for (int it = 0; it < 4; it++) {
        int idx = it * 512 + tid;
        int row = idx >> 4, seg = idx & 15;
        cp16(Bs + row * 136 + seg * 8, W + row * 384 + seg * 8);
    }
    CP_COMMIT();
    if (tid < 384) sb[tid] = bias[tid];

    // LN (gathered rows) -> As
    #pragma unroll
    for (int i = 0; i < 8; i++) {
        int r = i * 16 + wid;
        int src = win_row_to_token(m0 + r);
        float4 v = *(const float4*)(x + (size_t)src * 128 + lane * 4);
        float s  = v.x + v.y + v.z + v.w;
        float s2 = fmaf(v.x, v.x, fmaf(v.y, v.y, fmaf(v.z, v.z, v.w * v.w)));
        #pragma unroll
        for (int o = 16; o; o >>= 1) {
            s  += __shfl_xor_sync(0xffffffffu, s,  o);
            s2 += __shfl_xor_sync(0xffffffffu, s2, o);
        }
        float mu  = s * (1.0f / 128.0f);
        float var = s2 * (1.0f / 128.0f) - mu * mu;
        float inv = rsqrtf(var + 1e-5f);
        float4 gv = *(const float4*)(g + lane * 4);
        float4 bv = *(const float4*)(beta + lane * 4);
        uint2 u;
        u.x = packbf((v.x - mu) * inv * gv.x + bv.x, (v.y - mu) * inv * gv.y + bv.y);
        u.y = packbf((v.z - mu) * inv * gv.z + bv.z, (v.w - mu) * inv * gv.w + bv.w);
        *(uint2*)(As + r * 136 + lane * 4) = u;
    }

    uint32_t aAddr  = cvta_smem(As + (wm * 32 + (lane & 15)) * 136 + (lane >> 4) * 8);
    uint32_t bAddr0 = cvta_smem(Bs + (lane & 15) * 136 + wn * 32 + (lane >> 4) * 8);
    int gcol = lane >> 2, t4 = lane & 3;

    for (int c = 0; c < 3; c++) {
        CP_WAIT0();
        __syncthreads();
        if (c < 2) {
            __nv_bfloat16* dst = Bs + ((c + 1) & 1) * 17408;
            const __nv_bfloat16* src = W + (c + 1) * 128;
            #pragma unroll
            for (int it = 0; it < 4; it++) {
                int idx = it * 512 + tid;
                int row = idx >> 4, seg = idx & 15;
                cp16(dst + row * 136 + seg * 8, src + row * 384 + seg * 8);
            }
            CP_COMMIT();
        }

        float acc[2][4][4];
        #pragma unroll
        for (int mi = 0; mi < 2; mi++)
            #pragma unroll
            for (int ni = 0; ni < 4; ni++)
                #pragma unroll
                for (int q = 0; q < 4; q++) acc[mi][ni][q] = 0.0f;

        uint32_t bAddr = bAddr0 + (c & 1) * 34816u;
        #pragma unroll
        for (int s = 0; s < 8; s++) {
            uint32_t aF[2][4];
            #pragma unroll
            for (int mi = 0; mi < 2; mi++)
                ldmx4(aF[mi], aAddr + mi * 4352u + s * 32u);
            uint32_t bF[4][2];
            #pragma unroll
            for (int nq = 0; nq < 2; nq++) {
                uint32_t r[4];
                ldmx4t(r, bAddr + s * 4352u + nq * 32u);
                bF[2 * nq    ][0] = r[0]; bF[2 * nq    ][1] = r[1];
                bF[2 * nq + 1][0] = r[2]; bF[2 * nq + 1][1] = r[3];
            }
            #pragma unroll
            for (int mi = 0; mi < 2; mi++)
                #pragma unroll
                for (int ni = 0; ni < 4; ni++)
                    mma16816(acc[mi][ni], aF[mi], bF[ni]);
        }

        #pragma unroll
        for (int mi = 0; mi < 2; mi++) {
            int rl = wm * 32 + mi * 16 + gcol;
            #pragma unroll
            for (int ni = 0; ni < 4; ni++) {
                int cl = wn * 32 + ni * 8 + t4 * 2;
                float b0 = sb[c * 128 + cl], b1 = sb[c * 128 + cl + 1];
                *(uint32_t*)(qkv + (size_t)(m0 + rl) * 384 + c * 128 + cl) =
                    packbf(acc[mi][ni][0] + b0, acc[mi][ni][1] + b1);
                *(uint32_t*)(qkv + (size_t)(m0 + rl + 8) * 384 + c * 128 + cl) =
                    packbf(acc[mi][ni][2] + b0, acc[mi][ni][3] + b1);
            }
        }
        __syncthreads();
    }
}

// ---------------------------------------------------------------------------
// HMMA attention: one block per (window, head), 256 threads (8 warps x 16 rows).
// ---------------------------------------------------------------------------
#define ASMEM 30720

__global__ __launch_bounds__(256)
void attn_hmma(const __nv_bfloat16* __restrict__ qkv, const float* __restrict__ btab,
               __nv_bfloat16* __restrict__ ao) {
    extern __shared__ char smc[];
    __nv_bfloat16* Qs = (__nv_bfloat16*)(smc);
    __nv_bfloat16* Ks = (__nv_bfloat16*)(smc + 10240);
    __nv_bfloat16* Vs = (__nv_bfloat16*)(smc + 20480);

    int tid = threadIdx.x, warp = tid >> 5, lane = tid & 31;
    int g = lane >> 2, t4 = lane & 3;
    int win = blockIdx.x >> 2, head = blockIdx.x & 3;
    const float CEXP = 0.17677669529663687f * 1.4426950408889634f;
    const float* bt = btab + head * 10976;

    #pragma unroll
    for (int it = 0; it < 2; it++) {
        int idx = it * 256 + tid;
        int row = idx >> 2, seg = idx & 3;
        uint4 zq = make_uint4(0, 0, 0, 0), zk = zq, zv = zq;
        if (row < 98) {
            const __nv_bfloat16* base = qkv + (size_t)(win * 98 + row) * 384 + head * 32 + seg * 8;
            zq = *(const uint4*)(base);
            zk = *(const uint4*)(base + 128);
            zv = *(const uint4*)(base + 256);
        }
        *(uint4*)(Qs + row * 40 + seg * 8) = zq;
        *(uint4*)(Ks + row * 40 + seg * 8) = zk;
        *(uint4*)(Vs + row * 40 + seg * 8) = zv;
    }
    __syncthreads();

    uint32_t qAddr = cvta_smem(Qs + (warp * 16 + (lane & 15)) * 40 + (lane >> 4) * 8);
    uint32_t kAddr = cvta_smem(Ks + (lane & 15) * 40 + (lane >> 4) * 8);
    uint32_t vAddr = cvta_smem(Vs + (lane & 15) * 40 + (lane >> 4) * 8);

    float sacc[13][4];
    #pragma unroll
    for (int j = 0; j < 13; j++)
        #pragma unroll
        for (int q = 0; q < 4; q++) sacc[j][q] = 0.0f;

    #pragma unroll
    for (int ks = 0; ks < 32; ks += 16) {
        uint32_t aF[4];
        ldmx4(aF, qAddr + ks * 2u);
        #pragma unroll
        for (int j2 = 0; j2 < 7; j2++) {
            uint32_t r[4];
            ldmx4(r, kAddr + j2 * 1280u + ks * 2u);
            mma16816b(sacc[2 * j2], aF, r[0], r[2]);
            if (j2 < 6) mma16816b(sacc[2 * j2 + 1], aF, r[1], r[3]);
        }
    }

    int ra = warp * 16 + g, rb = ra + 8;
    bool oka = ra < 98, okb = rb < 98;
    float rsum0 = 0.0f, rsum1 = 0.0f;
    #pragma unroll
    for (int j = 0; j < 13; j++) {
        int c0 = 8 * j + 2 * t4;
        bool cv = c0 < 98;
        float e0 = 0.0f, e1 = 0.0f, e2 = 0.0f, e3 = 0.0f;
        if (cv && oka) {
            float2 bb = *(const float2*)(bt + ra * 112 + c0);
            e0 = exp2f(fmaf(sacc[j][0], CEXP, bb.x));
            e1 = exp2f(fmaf(sacc[j][1], CEXP, bb.y));
        }
        if (cv && okb) {
            float2 bb = *(const float2*)(bt + rb * 112 + c0);
            e2 = exp2f(fmaf(sacc[j][2], CEXP, bb.x));
            e3 = exp2f(fmaf(sacc[j][3], CEXP, bb.y));
        }
        sacc[j][0] = e0; sacc[j][1] = e1; sacc[j][2] = e2; sacc[j][3] = e3;
        rsum0 += e0 + e1;
        rsum1 += e2 + e3;
    }
    rsum0 += __shfl_xor_sync(0xffffffffu, rsum0, 1);
    rsum0 += __shfl_xor_sync(0xffffffffu, rsum0, 2);
    rsum1 += __shfl_xor_sync(0xffffffffu, rsum1, 1);
    rsum1 += __shfl_xor_sync(0xffffffffu, rsum1, 2);
    float inv0 = 1.0f / rsum0, inv1 = 1.0f / rsum1;

    float oacc[4][4];
    #pragma unroll
    for (int j = 0; j < 4; j++)
        #pragma unroll
        for (int q = 0; q < 4; q++) oacc[j][q] = 0.0f;

    #pragma unroll
    for (int ks2 = 0; ks2 < 7; ks2++) {
        uint32_t bV[4][2];
        #pragma unroll
        for (int nq = 0; nq < 2; nq++) {
            uint32_t r[4];
            ldmx4t(r, vAddr + ks2 * 1280u + nq * 32u);
            bV[2 * nq    ][0] = r[0]; bV[2 * nq    ][1] = r[1];
            bV[2 * nq + 1][0] = r[2]; bV[2 * nq + 1][1] = r[3];
        }
        uint32_t a[4];
        a[0] = packbf(sacc[2 * ks2][0], sacc[2 * ks2][1]);
        a[1] = packbf(sacc[2 * ks2][2], sacc[2 * ks2][3]);
        if (ks2 < 6) {
            a[2] = packbf(sacc[2 * ks2 + 1][0], sacc[2 * ks2 + 1][1]);
            a[3] = packbf(sacc[2 * ks2 + 1][2], sacc[2 * ks2 + 1][3]);
        } else { a[2] = 0u; a[3] = 0u; }
        #pragma unroll
        for (int j = 0; j < 4; j++)
            mma16816(oacc[j], a, bV[j]);
    }

    #pragma unroll
    for (int j = 0; j < 4; j++) {
        int c = head * 32 + 8 * j + 2 * t4;
        if (oka)
            *(uint32_t*)(ao + (size_t)(win * 98 + ra) * 128 + c) =
                packbf(oacc[j][0] * inv0, oacc[j][1] * inv0);
        if (okb)
            *(uint32_t*)(ao + (size_t)(win * 98 + rb) * 128 + c) =
                packbf(oacc[j][2] * inv1, oacc[j][3] * inv1);
    }
}

// ---------------------------------------------------------------------------
// Proj GEMM + residual (scatter). 512 threads, single K stage (K=128).
// ---------------------------------------------------------------------------
#define PJ_SMEM 69632   // As[128][136] + Bs[128][136] bf16

__global__ __launch_bounds__(512, 2)
void gemm_proj(const __nv_bfloat16* __restrict__ A, const __nv_bfloat16* __restrict__ W,
               const float* __restrict__ bias, const float* __restrict__ res,
               float* __restrict__ Cout) {
    extern __shared__ char smc[];
    __nv_bfloat16* As = (__nv_bfloat16*)(smc);
    __nv_bfloat16* Bs = (__nv_bfloat16*)(smc + 34816);
    __shared__ int   rowmap[128];
    __shared__ float sbias[128];

    int tid = threadIdx.x, lane = tid & 31, wid = tid >> 5;
    int wm = wid & 3, wn = wid >> 2;
    int m0 = blockIdx.x * 128;

    // stage A[128][128] and W[128][128] (stride 136)
    #pragma unroll
    for (int it = 0; it < 4; it++) {
        int idx = it * 512 + tid;
        int row = idx >> 4, seg = idx & 15;
        cp16(As + row * 136 + seg * 8, A + (size_t)(m0 + row) * 128 + seg * 8);
        cp16(Bs + row * 136 + seg * 8, W + (size_t)row * 128 + seg * 8);
    }
    CP_COMMIT();
    if (tid < 128) {
        sbias[tid] = bias[tid];
        rowmap[tid] = win_row_to_token(m0 + tid);
    }

    float acc[2][4][4];
    #pragma unroll
    for (int mi = 0; mi < 2; mi++)
        #pragma unroll
        for (int ni = 0; ni < 4; ni++)
            #pragma unroll
            for (int q = 0; q < 4; q++) acc[mi][ni][q] = 0.0f;

    uint32_t aAddr = cvta_smem(As + (wm * 32 + (lane & 15)) * 136 + (lane >> 4) * 8);
    uint32_t bAddr = cvta_smem(Bs + (lane & 15) * 136 + wn * 32 + (lane >> 4) * 8);

    CP_WAIT0();
    __syncthreads();

    #pragma unroll
    for (int s = 0; s < 8; s++) {
        uint32_t aF[2][4];
        #pragma unroll
        for (int mi = 0; mi < 2; mi++)
            ldmx4(aF[mi], aAddr + mi * 4352u + s * 32u);
        uint32_t bF[4][2];
        #pragma unroll
        for (int nq = 0; nq < 2; nq++) {
            uint32_t r[4];
            ldmx4t(r, bAddr + s * 4352u + nq * 32u);
            bF[2 * nq    ][0] = r[0]; bF[2 * nq    ][1] = r[1];
            bF[2 * nq + 1][0] = r[2]; bF[2 * nq + 1][1] = r[3];
        }
        #pragma unroll
        for (int mi = 0; mi < 2; mi++)
            #pragma unroll
            for (int ni = 0; ni < 4; ni++)
                mma16816(acc[mi][ni], aF[mi], bF[ni]);
    }

    int gcol = lane >> 2, t4 = lane & 3;
    #pragma unroll
    for (int mi = 0; mi < 2; mi++) {
        int rl = wm * 32 + mi * 16 + gcol;
        int r0 = rowmap[rl], r1 = rowmap[rl + 8];
        #pragma unroll
        for (int ni = 0; ni < 4; ni++) {
            int cl = wn * 32 + ni * 8 + t4 * 2;
            float b0 = sbias[cl], b1 = sbias[cl + 1];
            size_t o0 = (size_t)r0 * 128 + cl;
            size_t o1 = (size_t)r1 * 128 + cl;
            float2 q0 = *(const float2*)(res + o0);
            float2 q1 = *(const float2*)(res + o1);
            *(float2*)(Cout + o0) = make_float2(acc[mi][ni][0] + b0 + q0.x,
                                                acc[mi][ni][1] + b1 + q0.y);
            *(float2*)(Cout + o1) = make_float2(acc[mi][ni][2] + b0 + q1.x,
                                                acc[mi][ni][3] + b1 + q1.y);
        }
    }
}

// ---------------------------------------------------------------------------
// Fused LN2 + MLP1 + GELU + MLP2 + residual. 512 threads, 16 warps.
// ---------------------------------------------------------------------------
#define FM_AS 0
#define FM_HS 34816
#define FM_W1 69632                  // 2 x 34816
#define FM_W2 139264                 // 2 x 34816
#define FM_B1 208896                 // 512 floats
#define FM_B2 210944                 // 128 floats
#define FM_SMEM 211456

__global__ __launch_bounds__(512)
void fused_mlp(const float* __restrict__ y2, const float* __restrict__ g,
               const float* __restrict__ beta, const __nv_bfloat16* __restrict__ W1,
               const float* __restrict__ b1, const __nv_bfloat16* __restrict__ W2,
               const float* __restrict__ b2, float* __restrict__ out) {
    extern __shared__ char smc[];
    __nv_bfloat16* As  = (__nv_bfloat16*)(smc + FM_AS);
    __nv_bfloat16* Hs  = (__nv_bfloat16*)(smc + FM_HS);
    __nv_bfloat16* W1s = (__nv_bfloat16*)(smc + FM_W1);
    __nv_bfloat16* W2s = (__nv_bfloat16*)(smc + FM_W2);
    float* sb1 = (float*)(smc + FM_B1);
    float* sb2 = (float*)(smc + FM_B2);

    int tid = threadIdx.x, lane = tid & 31, wid = tid >> 5;
    int wm = wid & 3, wn = wid >> 2;
    int m0 = blockIdx.x * 128;

    // prefetch chunk 0 of W1, W2
    #pragma unroll
    for (int it = 0; it < 4; it++) {
        int idx = it * 512 + tid;
        int row = idx >> 4, seg = idx & 15;
        cp16(W1s + row * 136 + seg * 8, W1 + row * 512 + seg * 8);
        cp16(W2s + row * 136 + seg * 8, W2 + row * 128 + seg * 8);
    }
    CP_COMMIT();
    if (tid < 512) sb1[tid] = b1[tid];
    if (tid < 128) sb2[tid] = b2[tid];

    // LN2 -> As
    #pragma unroll
    for (int i = 0; i < 8; i++) {
        int r = i * 16 + wid;
        float4 v = *(const float4*)(y2 + (size_t)(m0 + r) * 128 + lane * 4);
        float s  = v.x + v.y + v.z + v.w;
        float s2 = fmaf(v.x, v.x, fmaf(v.y, v.y, fmaf(v.z, v.z, v.w * v.w)));
        #pragma unroll
        for (int o = 16; o; o >>= 1) {
            s  += __shfl_xor_sync(0xffffffffu, s,  o);
            s2 += __shfl_xor_sync(0xffffffffu, s2, o);
        }
        float mu  = s * (1.0f / 128.0f);
        float var = s2 * (1.0f / 128.0f) - mu * mu;
        float inv = rsqrtf(var + 1e-5f);
        float4 gv = *(const float4*)(g + lane * 4);
        float4 bv = *(const float4*)(beta + lane * 4);
        uint2 u;
        u.x = packbf((v.x - mu) * inv * gv.x + bv.x, (v.y - mu) * inv * gv.y + bv.y);
        u.y = packbf((v.z - mu) * inv * gv.z + bv.z, (v.w - mu) * inv * gv.w + bv.w);
        *(uint2*)(As + r * 136 + lane * 4) = u;
    }

    uint32_t aAddr   = cvta_smem(As + (wm * 32 + (lane & 15)) * 136 + (lane >> 4) * 8);
    uint32_t hAddrW  = cvta_smem(Hs + (wm * 32 + (lane & 15)) * 136 + (lane >> 4) * 8);
    uint32_t w1Addr0 = cvta_smem(W1s + (lane & 15) * 136 + wn * 32 + (lane >> 4) * 8);
    uint32_t w2Addr0 = cvta_smem(W2s + (lane & 15) * 136 + wn * 32 + (lane >> 4) * 8);
    int gcol = lane >> 2, t4 = lane & 3;

    float oacc[2][4][4];
    #pragma unroll
    for (int mi = 0; mi < 2; mi++)
        #pragma unroll
        for (int ni = 0; ni < 4; ni++)
            #pragma unroll
            for (int q = 0; q < 4; q++) oacc[mi][ni][q] = 0.0f;

    for (int c = 0; c < 4; c++) {
        CP_WAIT0();
        __syncthreads();
        if (c < 3) {
            __nv_bfloat16* d1 = W1s + ((c + 1) & 1) * 17408;
            __nv_bfloat16* d2 = W2s + ((c + 1) & 1) * 17408;
            const __nv_bfloat16* s1 = W1 + (c + 1) * 128;
            const __nv_bfloat16* s2 = W2 + (size_t)(c + 1) * 128 * 128;
            #pragma unroll
            for (int it = 0; it < 4; it++) {
                int idx = it * 512 + tid;
                int row = idx >> 4, seg = idx & 15;
                cp16(d1 + row * 136 + seg * 8, s1 + row * 512 + seg * 8);
                cp16(d2 + row * 136 + seg * 8, s2 + row * 128 + seg * 8);
            }
            CP_COMMIT();
        }

        // H = A @ W1c
        float hacc[2][4][4];
        #pragma unroll
        for (int mi = 0; mi < 2; mi++)
            #pragma unroll
            for (int ni = 0; ni < 4; ni++)
                #pragma unroll
                for (int q = 0; q < 4; q++) hacc[mi][ni][q] = 0.0f;

        uint32_t w1Addr = w1Addr0 + (c & 1) * 34816u;
        #pragma unroll
        for (int s = 0; s < 8; s++) {
            uint32_t aF[2][4];
            #pragma unroll
            for (int mi = 0; mi < 2; mi++)
                ldmx4(aF[mi], aAddr + mi * 4352u + s * 32u);
            uint32_t bF[4][2];
            #pragma unroll
            for (int nq = 0; nq < 2; nq++) {
                uint32_t r[4];
                ldmx4t(r, w1Addr + s * 4352u + nq * 32u);
                bF[2 * nq    ][0] = r[0]; bF[2 * nq    ][1] = r[1];
                bF[2 * nq + 1][0] = r[2]; bF[2 * nq + 1][1] = r[3];
            }
            #pragma unroll
            for (int mi = 0; mi < 2; mi++)
                #pragma unroll
                for (int ni = 0; ni < 4; ni++)
                    mma16816(hacc[mi][ni], aF[mi], bF[ni]);
        }

        // gelu + pack -> Hs
        #pragma unroll
        for (int mi = 0; mi < 2; mi++) {
            int rl = wm * 32 + mi * 16 + gcol;
            #pragma unroll
            for (int ni = 0; ni < 4; ni++) {
                int cl = wn * 32 + ni * 8 + t4 * 2;
                float b0 = sb1[c * 128 + cl], b1v = sb1[c * 128 + cl + 1];
                *(uint32_t*)(Hs + rl * 136 + cl) =
                    packbf(gelu_exact(hacc[mi][ni][0] + b0), gelu_exact(hacc[mi][ni][1] + b1v));
                *(uint32_t*)(Hs + (rl + 8) * 136 + cl) =
                    packbf(gelu_exact(hacc[mi][ni][2] + b0), gelu_exact(hacc[mi][ni][3] + b1v));
            }
        }
        __syncthreads();

        // oacc += H @ W2c
        uint32_t w2Addr = w2Addr0 + (c & 1) * 34816u;
        #pragma unroll
        for (int s = 0; s < 8; s++) {
            uint32_t aF[2][4];
            #pragma unroll
            for (int mi = 0; mi < 2; mi++)
                ldmx4(aF[mi], hAddrW + mi * 4352u + s * 32u);
            uint32_t bF[4][2];
            #pragma unroll
            for (int nq = 0; nq < 2; nq++) {
                uint32_t r[4];
                ldmx4t(r, w2Addr + s * 4352u + nq * 32u);
                bF[2 * nq    ][0] = r[0]; bF[2 * nq    ][1] = r[1];
                bF[2 * nq + 1][0] = r[2]; bF[2 * nq + 1][1] = r[3];
            }
            #pragma unroll
            for (int mi = 0; mi < 2; mi++)
                #pragma unroll
                for (int ni = 0; ni < 4; ni++)
                    mma16816(oacc[mi][ni], aF[mi], bF[ni]);
        }
    }

    // epilogue: +b2 + residual y2 -> out fp32
    #pragma unroll
    for (int mi = 0; mi < 2; mi++) {
        int rl = wm * 32 + mi * 16 + gcol;
        #pragma unroll
        for (int ni = 0; ni < 4; ni++) {
            int cl = wn * 32 + ni * 8 + t4 * 2;
            float b0 = sb2[cl], b1v = sb2[cl + 1];
            size_t o0 = (size_t)(m0 + rl) * 128 + cl;
            size_t o1 = (size_t)(m0 + rl + 8) * 128 + cl;
            float2 q0 = *(const float2*)(y2 + o0);
            float2 q1 = *(const float2*)(y2 + o1);
            *(float2*)(out + o0) = make_float2(oacc[mi][ni][0] + b0 + q0.x,
                                               oacc[mi][ni][1] + b1v + q0.y);
            *(float2*)(out + o1) = make_float2(oacc[mi][ni][2] + b0 + q1.x,
                                               oacc[mi][ni][3] + b1v + q1.y);
        }
    }
}

// ---------------------------------------------------------------------------
extern "C" void kernel_launch(void* const* d_in, const int* in_sizes, int n_in,
                              void* d_out, int out_size) {
    (void)in_sizes; (void)n_in; (void)out_size;
    const float* x       = (const float*)d_in[0];
    const int*   rel_idx = (const int*)  d_in[1];
    const float* rpb     = (const float*)d_in[2];
    const float* qkv_w   = (const float*)d_in[3];
    const float* qkv_b   = (const float*)d_in[4];
    const float* proj_w  = (const float*)d_in[5];
    const float* proj_b  = (const float*)d_in[6];
    const float* ln1_g   = (const float*)d_in[7];
    const float* ln1_b   = (const float*)d_in[8];
    const float* ln2_g   = (const float*)d_in[9];
    const float* ln2_b   = (const float*)d_in[10];
    const float* mlp_w1  = (const float*)d_in[11];
    const float* mlp_b1  = (const float*)d_in[12];
    const float* mlp_w2  = (const float*)d_in[13];
    const float* mlp_b2  = (const float*)d_in[14];
    float* out = (float*)d_out;

    __nv_bfloat16 *qkvb, *ao, *wt;
    float *y2, *btab;
    cudaGetSymbolAddress((void**)&qkvb, g_qkv);
    cudaGetSymbolAddress((void**)&ao,   g_ao);
    cudaGetSymbolAddress((void**)&y2,   g_y2);
    cudaGetSymbolAddress((void**)&wt,   g_wt);
    cudaGetSymbolAddress((void**)&btab, g_btab);
    __nv_bfloat16* wt_qkv = wt;             // [128][384]
    __nv_bfloat16* wt_prj = wt + 49152;     // [128][128]
    __nv_bfloat16* wt_m1  = wt + 65536;     // [128][512]
    __nv_bfloat16* wt_m2  = wt + 131072;    // [512][128]

    cudaFuncSetAttribute(ln_qkv,    cudaFuncAttributeMaxDynamicSharedMemorySize, LQ_SMEM);
    cudaFuncSetAttribute(attn_hmma, cudaFuncAttributeMaxDynamicSharedMemorySize, ASMEM);
    cudaFuncSetAttribute(gemm_proj, cudaFuncAttributeMaxDynamicSharedMemorySize, PJ_SMEM);
    cudaFuncSetAttribute(fused_mlp, cudaFuncAttributeMaxDynamicSharedMemorySize, FM_SMEM);

    prep_all<<<940, 256>>>(qkv_w, proj_w, mlp_w1, mlp_w2, rel_idx, rpb, wt, btab);
    ln_qkv<<<784, 512, LQ_SMEM>>>(x, ln1_g, ln1_b, wt_qkv, qkv_b, qkvb);
    attn_hmma<<<4096, 256, ASMEM>>>(qkvb, btab, ao);
    gemm_proj<<<784, 512, PJ_SMEM>>>(ao, wt_prj, proj_b, x, y2);
    fused_mlp<<<784, 512, FM_SMEM>>>(y2, ln2_g, ln2_b, wt_m1, mlp_b1, wt_m2, mlp_b2, out);
}